// round 1
// baseline (speedup 1.0000x reference)
#include <cuda_runtime.h>
#include <math.h>

#define SEQ   2048
#define BATCH 2
#define DIM   1024
#define HEADS 16
#define DKH   64
#define NROW  (SEQ*BATCH)   // 4096
#define LDGL  (BATCH*DIM)   // 2048 floats between consecutive s

// ---------------- scratch (device globals; no allocation allowed) ----------------
__device__ float g_qx[NROW*DIM];
__device__ float g_kx[NROW*DIM];
__device__ float g_vx[NROW*DIM];
__device__ float g_qc[NROW*DIM];
__device__ float g_kc[NROW*DIM];
__device__ float g_ctx[NROW*DIM];

// ---------------- generic SGEMM: C[M=4096,N=1024] = A @ W + bias ----------------
struct Gemm1 { const float* A; const float* W; const float* bias; float* C; };
struct Gemm5 { Gemm1 g[5]; };

__global__ __launch_bounds__(256)
void sgemm_kernel(Gemm5 args) {
    __shared__ float As[8*128];   // As[k][m]
    __shared__ float Bs[8*128];   // Bs[k][n]
    Gemm1 ga = args.g[blockIdx.z];
    const float* __restrict__ A    = ga.A;
    const float* __restrict__ W    = ga.W;
    const float* __restrict__ bias = ga.bias;
    float* __restrict__ C          = ga.C;

    const int t  = threadIdx.x;
    const int tx = t & 15, ty = t >> 4;
    const int m0 = blockIdx.y * 128, n0 = blockIdx.x * 128;

    const int arow = t >> 1, kseg = (t & 1) * 4;
    const int brow = t >> 5, bcol = (t & 31) * 4;

    float acc[8][8];
#pragma unroll
    for (int i = 0; i < 8; i++)
#pragma unroll
        for (int j = 0; j < 8; j++) acc[i][j] = 0.f;

    for (int k0 = 0; k0 < 1024; k0 += 8) {
        float4 av = *(const float4*)&A[(size_t)(m0 + arow) * 1024 + k0 + kseg];
        float4 bv = *(const float4*)&W[(size_t)(k0 + brow) * 1024 + n0 + bcol];
        __syncthreads();                 // previous iter compute done before overwrite
        As[(kseg+0)*128 + arow] = av.x;
        As[(kseg+1)*128 + arow] = av.y;
        As[(kseg+2)*128 + arow] = av.z;
        As[(kseg+3)*128 + arow] = av.w;
        *(float4*)&Bs[brow*128 + bcol] = bv;
        __syncthreads();
#pragma unroll
        for (int kk = 0; kk < 8; kk++) {
            float a[8], b[8];
            *(float4*)&a[0] = *(float4*)&As[kk*128 + ty*8];
            *(float4*)&a[4] = *(float4*)&As[kk*128 + ty*8 + 4];
            *(float4*)&b[0] = *(float4*)&Bs[kk*128 + tx*8];
            *(float4*)&b[4] = *(float4*)&Bs[kk*128 + tx*8 + 4];
#pragma unroll
            for (int i = 0; i < 8; i++)
#pragma unroll
                for (int j = 0; j < 8; j++) acc[i][j] += a[i]*b[j];
        }
    }

#pragma unroll
    for (int i = 0; i < 8; i++) {
        int m = m0 + ty*8 + i;
#pragma unroll
        for (int j = 0; j < 8; j += 4) {
            int n = n0 + tx*8 + j;
            float4 o;
            o.x = acc[i][j+0] + bias[n+0];
            o.y = acc[i][j+1] + bias[n+1];
            o.z = acc[i][j+2] + bias[n+2];
            o.w = acc[i][j+3] + bias[n+3];
            *(float4*)&C[(size_t)m*1024 + n] = o;
        }
    }
}

// ---------------- lambda gate + mix (in place) ----------------
// blockIdx.y == 0: q path (g_qx,g_qc,W_Vqx,W_Vqc) -> g_qx
// blockIdx.y == 1: k path (g_kx,g_kc,W_Vkx,W_Vkc) -> g_kx
__global__ __launch_bounds__(256)
void lam_mix_kernel(const float* __restrict__ Wvqx, const float* __restrict__ bvqx,
                    const float* __restrict__ Wvqc, const float* __restrict__ bvqc,
                    const float* __restrict__ Wvkx, const float* __restrict__ bvkx,
                    const float* __restrict__ Wvkc, const float* __restrict__ bvkc) {
    const int r   = blockIdx.x;
    const bool isK = (blockIdx.y != 0);
    float* a = isK ? g_kx : g_qx;
    float* c = isK ? g_kc : g_qc;
    const float* Wa = isK ? Wvkx : Wvqx;
    const float* Wc = isK ? Wvkc : Wvqc;
    const float bsum = isK ? (bvkx[0] + bvkc[0]) : (bvqx[0] + bvqc[0]);

    const int t = threadIdx.x;
    float av[4], cv[4];
    float part = 0.f;
#pragma unroll
    for (int i = 0; i < 4; i++) {
        int d = t + i*256;
        av[i] = a[(size_t)r*1024 + d];
        cv[i] = c[(size_t)r*1024 + d];
        part += av[i]*Wa[d] + cv[i]*Wc[d];
    }
    __shared__ float red[256];
    red[t] = part;
    __syncthreads();
    for (int s = 128; s > 0; s >>= 1) {
        if (t < s) red[t] += red[t+s];
        __syncthreads();
    }
    float lam = 1.f / (1.f + __expf(-(red[0] + bsum)));
#pragma unroll
    for (int i = 0; i < 4; i++) {
        int d = t + i*256;
        a[(size_t)r*1024 + d] = av[i] + lam*(cv[i] - av[i]);
    }
}

// ---------------- fp32 flash attention ----------------
// grid: (32 q-tiles, H, B); block: 256 = 16x16. tile 64x64, DK=64.
// smem: QT[d][row] 16KB | KT[d][col] (reused as swizzled P[col][row]) 16KB | Vs[k][d] 16KB
__global__ __launch_bounds__(256)
void flash_kernel() {
    extern __shared__ float sm[];
    float* QT = sm;
    float* KT = sm + 4096;
    float* Vs = sm + 8192;

    const int tid = threadIdx.x;
    const int tx = tid & 15, ty = tid >> 4;
    const int qt = blockIdx.x, h = blockIdx.y, b = blockIdx.z;
    const int q0 = qt * 64;
    const size_t base = (size_t)b * DIM + (size_t)h * DKH;

    // load Q tile transposed (lanes -> rows: STS conflict-free)
    {
        int row = tid & 63, cg = tid >> 6;   // cg in 0..3, 16 floats each
#pragma unroll
        for (int j = 0; j < 4; j++) {
            float4 v4 = *(const float4*)&g_qx[base + (size_t)(q0+row)*LDGL + cg*16 + j*4];
            QT[(cg*16 + j*4 + 0)*64 + row] = v4.x;
            QT[(cg*16 + j*4 + 1)*64 + row] = v4.y;
            QT[(cg*16 + j*4 + 2)*64 + row] = v4.z;
            QT[(cg*16 + j*4 + 3)*64 + row] = v4.w;
        }
    }

    float m_i[4], l_i[4], o[4][4];
#pragma unroll
    for (int r = 0; r < 4; r++) {
        m_i[r] = -1e30f; l_i[r] = 0.f;
#pragma unroll
        for (int c = 0; c < 4; c++) o[r][c] = 0.f;
    }

    for (int kt = 0; kt < 32; kt++) {
        const int k0 = kt * 64;
        __syncthreads();   // previous iteration's PV reads finished

        // K tile transposed
        {
            int row = tid & 63, cg = tid >> 6;
#pragma unroll
            for (int j = 0; j < 4; j++) {
                float4 v4 = *(const float4*)&g_kx[base + (size_t)(k0+row)*LDGL + cg*16 + j*4];
                KT[(cg*16 + j*4 + 0)*64 + row] = v4.x;
                KT[(cg*16 + j*4 + 1)*64 + row] = v4.y;
                KT[(cg*16 + j*4 + 2)*64 + row] = v4.z;
                KT[(cg*16 + j*4 + 3)*64 + row] = v4.w;
            }
        }
        // V tile row-major (coalesced LDG, conflict-free STS)
        {
            int vr = tid >> 4, vc4 = tid & 15;
#pragma unroll
            for (int j = 0; j < 4; j++) {
                int row = vr + j*16;
                float4 v4 = *(const float4*)&g_vx[base + (size_t)(k0+row)*LDGL + vc4*4];
                *(float4*)&Vs[row*64 + vc4*4] = v4;
            }
        }
        __syncthreads();

        // scores: s[r][c] = Q[ty*4+r] . K[tx*4+c]
        float s[4][4];
#pragma unroll
        for (int r = 0; r < 4; r++)
#pragma unroll
            for (int c = 0; c < 4; c++) s[r][c] = 0.f;
#pragma unroll 8
        for (int d = 0; d < 64; d++) {
            float4 qv = *(float4*)&QT[d*64 + ty*4];
            float4 kv = *(float4*)&KT[d*64 + tx*4];
            float qa[4] = {qv.x, qv.y, qv.z, qv.w};
            float ka[4] = {kv.x, kv.y, kv.z, kv.w};
#pragma unroll
            for (int r = 0; r < 4; r++)
#pragma unroll
                for (int c = 0; c < 4; c++) s[r][c] += qa[r]*ka[c];
        }
#pragma unroll
        for (int r = 0; r < 4; r++)
#pragma unroll
            for (int c = 0; c < 4; c++) s[r][c] *= 0.125f;   // 1/sqrt(64)

        __syncthreads();   // done reading KT before overwriting with P

        // online softmax update (row reductions across the 16 tx lanes)
        float p[4][4];
#pragma unroll
        for (int r = 0; r < 4; r++) {
            float mt = fmaxf(fmaxf(s[r][0], s[r][1]), fmaxf(s[r][2], s[r][3]));
            mt = fmaxf(mt, __shfl_xor_sync(0xffffffffu, mt, 1));
            mt = fmaxf(mt, __shfl_xor_sync(0xffffffffu, mt, 2));
            mt = fmaxf(mt, __shfl_xor_sync(0xffffffffu, mt, 4));
            mt = fmaxf(mt, __shfl_xor_sync(0xffffffffu, mt, 8));
            float mnew = fmaxf(m_i[r], mt);
            float corr = __expf(m_i[r] - mnew);
            float ps = 0.f;
#pragma unroll
            for (int c = 0; c < 4; c++) {
                p[r][c] = __expf(s[r][c] - mnew);
                ps += p[r][c];
            }
            ps += __shfl_xor_sync(0xffffffffu, ps, 1);
            ps += __shfl_xor_sync(0xffffffffu, ps, 2);
            ps += __shfl_xor_sync(0xffffffffu, ps, 4);
            ps += __shfl_xor_sync(0xffffffffu, ps, 8);
            l_i[r] = l_i[r]*corr + ps;
            m_i[r] = mnew;
#pragma unroll
            for (int c = 0; c < 4; c++) o[r][c] *= corr;
        }

        // store P into KT buffer, layout P[kcol][qrow] with qgroup XOR-swizzle (ty^tx)
#pragma unroll
        for (int c = 0; c < 4; c++) {
            float4 w = make_float4(p[0][c], p[1][c], p[2][c], p[3][c]);
            *(float4*)&KT[(tx*4 + c)*64 + ((ty ^ tx) * 4)] = w;
        }
        __syncthreads();

        // PV: o[r][c] += sum_k P[k][ty*4+r] * V[k][tx*4+c]
#pragma unroll 8
        for (int kk = 0; kk < 64; kk++) {
            float4 pv = *(float4*)&KT[kk*64 + ((ty ^ (kk >> 2)) * 4)];
            float4 vv = *(float4*)&Vs[kk*64 + tx*4];
            float pa[4] = {pv.x, pv.y, pv.z, pv.w};
            float va[4] = {vv.x, vv.y, vv.z, vv.w};
#pragma unroll
            for (int r = 0; r < 4; r++)
#pragma unroll
                for (int c = 0; c < 4; c++) o[r][c] += pa[r]*va[c];
        }
    }

    // write ctx in [ (s*B+b)*D + h*64 + d ] layout
#pragma unroll
    for (int r = 0; r < 4; r++) {
        float inv = 1.f / l_i[r];
        int srow = q0 + ty*4 + r;
        float4 w = make_float4(o[r][0]*inv, o[r][1]*inv, o[r][2]*inv, o[r][3]*inv);
        *(float4*)&g_ctx[base + (size_t)srow*LDGL + tx*4] = w;
    }
}

// ---------------- launch ----------------
extern "C" void kernel_launch(void* const* d_in, const int* in_sizes, int n_in,
                              void* d_out, int out_size) {
    const float* qx   = (const float*)d_in[0];
    const float* kx   = (const float*)d_in[1];
    const float* vx   = (const float*)d_in[2];
    const float* qc   = (const float*)d_in[3];
    const float* kc   = (const float*)d_in[4];
    const float* W_qx = (const float*)d_in[5];
    const float* b_qx = (const float*)d_in[6];
    const float* W_kx = (const float*)d_in[7];
    const float* b_kx = (const float*)d_in[8];
    const float* W_vx = (const float*)d_in[9];
    const float* b_vx = (const float*)d_in[10];
    const float* W_qc = (const float*)d_in[11];
    const float* b_qc = (const float*)d_in[12];
    const float* W_kc = (const float*)d_in[13];
    const float* b_kc = (const float*)d_in[14];
    const float* W_out= (const float*)d_in[15];
    const float* b_out= (const float*)d_in[16];
    const float* W_Vqx= (const float*)d_in[17];
    const float* b_Vqx= (const float*)d_in[18];
    const float* W_Vqc= (const float*)d_in[19];
    const float* b_Vqc= (const float*)d_in[20];
    const float* W_Vkx= (const float*)d_in[21];
    const float* b_Vkx= (const float*)d_in[22];
    const float* W_Vkc= (const float*)d_in[23];
    const float* b_Vkc= (const float*)d_in[24];

    float *p_qx, *p_kx, *p_vx, *p_qc, *p_kc, *p_ctx;
    cudaGetSymbolAddress((void**)&p_qx,  g_qx);
    cudaGetSymbolAddress((void**)&p_kx,  g_kx);
    cudaGetSymbolAddress((void**)&p_vx,  g_vx);
    cudaGetSymbolAddress((void**)&p_qc,  g_qc);
    cudaGetSymbolAddress((void**)&p_kc,  g_kc);
    cudaGetSymbolAddress((void**)&p_ctx, g_ctx);

    // 1) five input projections, batched over blockIdx.z
    Gemm5 ga;
    ga.g[0] = {qx, W_qx, b_qx, p_qx};
    ga.g[1] = {kx, W_kx, b_kx, p_kx};
    ga.g[2] = {vx, W_vx, b_vx, p_vx};
    ga.g[3] = {qc, W_qc, b_qc, p_qc};
    ga.g[4] = {kc, W_kc, b_kc, p_kc};
    sgemm_kernel<<<dim3(8, 32, 5), 256>>>(ga);

    // 2) lambda gates + mixing (in place into g_qx / g_kx)
    lam_mix_kernel<<<dim3(NROW, 2), 256>>>(W_Vqx, b_Vqx, W_Vqc, b_Vqc,
                                           W_Vkx, b_Vkx, W_Vkc, b_Vkc);

    // 3) attention
    flash_kernel<<<dim3(32, HEADS, BATCH), 256, 49152>>>();

    // 4) output projection straight into d_out
    Gemm5 go;
    go.g[0] = {p_ctx, W_out, b_out, (float*)d_out};
    go.g[1] = go.g[0]; go.g[2] = go.g[0]; go.g[3] = go.g[0]; go.g[4] = go.g[0];
    sgemm_kernel<<<dim3(8, 32, 1), 256>>>(go);
}

// round 2
// speedup vs baseline: 1.0534x; 1.0534x over previous
#include <cuda_runtime.h>
#include <math.h>

#define SEQ   2048
#define BATCH 2
#define DIM   1024
#define HEADS 16
#define DKH   64
#define NROW  (SEQ*BATCH)   // 4096
#define LDGL  (BATCH*DIM)   // 2048 floats between consecutive s

typedef unsigned long long u64;

// ---------------- packed f32x2 helpers ----------------
__device__ __forceinline__ u64 pk2(float x, float y) {
    u64 r; asm("mov.b64 %0, {%1,%2};" : "=l"(r) : "f"(x), "f"(y)); return r;
}
__device__ __forceinline__ u64 bcast2(float x) {
    u64 r; asm("mov.b64 %0, {%1,%1};" : "=l"(r) : "f"(x)); return r;
}
__device__ __forceinline__ u64 fma2(u64 a, u64 b, u64 c) {
    u64 d; asm("fma.rn.f32x2 %0, %1, %2, %3;" : "=l"(d) : "l"(a), "l"(b), "l"(c)); return d;
}
__device__ __forceinline__ u64 mul2(u64 a, u64 b) {
    u64 d; asm("mul.rn.f32x2 %0, %1, %2;" : "=l"(d) : "l"(a), "l"(b)); return d;
}
__device__ __forceinline__ float2 upk(u64 v) {
    float2 f; asm("mov.b64 {%0,%1}, %2;" : "=f"(f.x), "=f"(f.y) : "l"(v)); return f;
}

// ---------------- scratch (device globals; no allocation allowed) ----------------
__device__ float g_qx[NROW*DIM];
__device__ float g_kx[NROW*DIM];
__device__ float g_vx[NROW*DIM];
__device__ float g_qc[NROW*DIM];
__device__ float g_kc[NROW*DIM];
__device__ float g_ctx[NROW*DIM];

// ---------------- generic SGEMM: C[M=4096,N=1024] = A @ W + bias ----------------
struct Gemm1 { const float* A; const float* W; const float* bias; float* C; };
struct Gemm5 { Gemm1 g[5]; };

__global__ __launch_bounds__(256)
void sgemm_kernel(Gemm5 args) {
    __shared__ float As[8*128];   // As[k][m]
    __shared__ float Bs[8*128];   // Bs[k][n]
    Gemm1 ga = args.g[blockIdx.z];
    const float* __restrict__ A    = ga.A;
    const float* __restrict__ W    = ga.W;
    const float* __restrict__ bias = ga.bias;
    float* __restrict__ C          = ga.C;

    const int t  = threadIdx.x;
    const int tx = t & 15, ty = t >> 4;
    const int m0 = blockIdx.y * 128, n0 = blockIdx.x * 128;

    const int arow = t >> 1, kseg = (t & 1) * 4;
    const int brow = t >> 5, bcol = (t & 31) * 4;

    u64 acc[8][4];   // acc[i][j2] = (C[i][2*j2], C[i][2*j2+1])
#pragma unroll
    for (int i = 0; i < 8; i++)
#pragma unroll
        for (int j = 0; j < 4; j++) acc[i][j] = 0ull;   // (0.f,0.f)

    for (int k0 = 0; k0 < 1024; k0 += 8) {
        float4 av = *(const float4*)&A[(size_t)(m0 + arow) * 1024 + k0 + kseg];
        float4 bv = *(const float4*)&W[(size_t)(k0 + brow) * 1024 + n0 + bcol];
        __syncthreads();                 // previous iter compute done before overwrite
        As[(kseg+0)*128 + arow] = av.x;
        As[(kseg+1)*128 + arow] = av.y;
        As[(kseg+2)*128 + arow] = av.z;
        As[(kseg+3)*128 + arow] = av.w;
        *(float4*)&Bs[brow*128 + bcol] = bv;
        __syncthreads();
#pragma unroll
        for (int kk = 0; kk < 8; kk++) {
            float a[8];
            *(float4*)&a[0] = *(float4*)&As[kk*128 + ty*8];
            *(float4*)&a[4] = *(float4*)&As[kk*128 + ty*8 + 4];
            ulonglong2 bp0 = *(ulonglong2*)&Bs[kk*128 + tx*8];
            ulonglong2 bp1 = *(ulonglong2*)&Bs[kk*128 + tx*8 + 4];
            u64 bb[4] = {bp0.x, bp0.y, bp1.x, bp1.y};
#pragma unroll
            for (int i = 0; i < 8; i++) {
                u64 ai = bcast2(a[i]);
#pragma unroll
                for (int j = 0; j < 4; j++) acc[i][j] = fma2(ai, bb[j], acc[i][j]);
            }
        }
    }

#pragma unroll
    for (int i = 0; i < 8; i++) {
        int m = m0 + ty*8 + i;
#pragma unroll
        for (int j = 0; j < 2; j++) {
            int n = n0 + tx*8 + j*4;
            float2 p0 = upk(acc[i][j*2+0]);
            float2 p1 = upk(acc[i][j*2+1]);
            float4 o;
            o.x = p0.x + bias[n+0];
            o.y = p0.y + bias[n+1];
            o.z = p1.x + bias[n+2];
            o.w = p1.y + bias[n+3];
            *(float4*)&C[(size_t)m*1024 + n] = o;
        }
    }
}

// ---------------- lambda gate + mix (in place) ----------------
__global__ __launch_bounds__(256)
void lam_mix_kernel(const float* __restrict__ Wvqx, const float* __restrict__ bvqx,
                    const float* __restrict__ Wvqc, const float* __restrict__ bvqc,
                    const float* __restrict__ Wvkx, const float* __restrict__ bvkx,
                    const float* __restrict__ Wvkc, const float* __restrict__ bvkc) {
    const int r   = blockIdx.x;
    const bool isK = (blockIdx.y != 0);
    float* a = isK ? g_kx : g_qx;
    float* c = isK ? g_kc : g_qc;
    const float* Wa = isK ? Wvkx : Wvqx;
    const float* Wc = isK ? Wvkc : Wvqc;
    const float bsum = isK ? (bvkx[0] + bvkc[0]) : (bvqx[0] + bvqc[0]);

    const int t = threadIdx.x;
    float av[4], cv[4];
    float part = 0.f;
#pragma unroll
    for (int i = 0; i < 4; i++) {
        int d = t + i*256;
        av[i] = a[(size_t)r*1024 + d];
        cv[i] = c[(size_t)r*1024 + d];
        part += av[i]*Wa[d] + cv[i]*Wc[d];
    }
    __shared__ float red[256];
    red[t] = part;
    __syncthreads();
    for (int s = 128; s > 0; s >>= 1) {
        if (t < s) red[t] += red[t+s];
        __syncthreads();
    }
    float lam = 1.f / (1.f + __expf(-(red[0] + bsum)));
#pragma unroll
    for (int i = 0; i < 4; i++) {
        int d = t + i*256;
        a[(size_t)r*1024 + d] = av[i] + lam*(cv[i] - av[i]);
    }
}

// ---------------- fp32 flash attention (f32x2-packed math) ----------------
// grid: (32 q-tiles, H, B); block: 256 = 16x16. tile 64x64, DK=64.
__global__ __launch_bounds__(256)
void flash_kernel() {
    extern __shared__ float sm[];
    float* QT = sm;
    float* KT = sm + 4096;
    float* Vs = sm + 8192;

    const int tid = threadIdx.x;
    const int tx = tid & 15, ty = tid >> 4;
    const int qt = blockIdx.x, h = blockIdx.y, b = blockIdx.z;
    const int q0 = qt * 64;
    const size_t base = (size_t)b * DIM + (size_t)h * DKH;

    // load Q tile transposed
    {
        int row = tid & 63, cg = tid >> 6;
#pragma unroll
        for (int j = 0; j < 4; j++) {
            float4 v4 = *(const float4*)&g_qx[base + (size_t)(q0+row)*LDGL + cg*16 + j*4];
            QT[(cg*16 + j*4 + 0)*64 + row] = v4.x;
            QT[(cg*16 + j*4 + 1)*64 + row] = v4.y;
            QT[(cg*16 + j*4 + 2)*64 + row] = v4.z;
            QT[(cg*16 + j*4 + 3)*64 + row] = v4.w;
        }
    }

    float m_i[4], l_i[4];
    u64 o2[4][2];   // o2[r][c2] packs (o[r][2c2], o[r][2c2+1])
#pragma unroll
    for (int r = 0; r < 4; r++) {
        m_i[r] = -1e30f; l_i[r] = 0.f;
        o2[r][0] = 0ull; o2[r][1] = 0ull;
    }

    for (int kt = 0; kt < 32; kt++) {
        const int k0 = kt * 64;
        __syncthreads();

        // K tile transposed
        {
            int row = tid & 63, cg = tid >> 6;
#pragma unroll
            for (int j = 0; j < 4; j++) {
                float4 v4 = *(const float4*)&g_kx[base + (size_t)(k0+row)*LDGL + cg*16 + j*4];
                KT[(cg*16 + j*4 + 0)*64 + row] = v4.x;
                KT[(cg*16 + j*4 + 1)*64 + row] = v4.y;
                KT[(cg*16 + j*4 + 2)*64 + row] = v4.z;
                KT[(cg*16 + j*4 + 3)*64 + row] = v4.w;
            }
        }
        // V tile row-major
        {
            int vr = tid >> 4, vc4 = tid & 15;
#pragma unroll
            for (int j = 0; j < 4; j++) {
                int row = vr + j*16;
                float4 v4 = *(const float4*)&g_vx[base + (size_t)(k0+row)*LDGL + vc4*4];
                *(float4*)&Vs[row*64 + vc4*4] = v4;
            }
        }
        __syncthreads();

        // scores: s[r][c] = Q[ty*4+r] . K[tx*4+c] — packed over c
        u64 s2[4][2];
#pragma unroll
        for (int r = 0; r < 4; r++) { s2[r][0] = 0ull; s2[r][1] = 0ull; }
#pragma unroll 8
        for (int d = 0; d < 64; d++) {
            float4 qv = *(float4*)&QT[d*64 + ty*4];
            ulonglong2 kp = *(ulonglong2*)&KT[d*64 + tx*4];
            float qa[4] = {qv.x, qv.y, qv.z, qv.w};
#pragma unroll
            for (int r = 0; r < 4; r++) {
                u64 qb = bcast2(qa[r]);
                s2[r][0] = fma2(qb, kp.x, s2[r][0]);
                s2[r][1] = fma2(qb, kp.y, s2[r][1]);
            }
        }
        float s[4][4];
#pragma unroll
        for (int r = 0; r < 4; r++) {
            float2 lo = upk(s2[r][0]), hi = upk(s2[r][1]);
            s[r][0] = lo.x*0.125f; s[r][1] = lo.y*0.125f;
            s[r][2] = hi.x*0.125f; s[r][3] = hi.y*0.125f;
        }

        __syncthreads();   // done reading KT before overwriting with P

        // online softmax update
        float p[4][4];
#pragma unroll
        for (int r = 0; r < 4; r++) {
            float mt = fmaxf(fmaxf(s[r][0], s[r][1]), fmaxf(s[r][2], s[r][3]));
            mt = fmaxf(mt, __shfl_xor_sync(0xffffffffu, mt, 1));
            mt = fmaxf(mt, __shfl_xor_sync(0xffffffffu, mt, 2));
            mt = fmaxf(mt, __shfl_xor_sync(0xffffffffu, mt, 4));
            mt = fmaxf(mt, __shfl_xor_sync(0xffffffffu, mt, 8));
            float mnew = fmaxf(m_i[r], mt);
            float corr = __expf(m_i[r] - mnew);
            float ps = 0.f;
#pragma unroll
            for (int c = 0; c < 4; c++) {
                p[r][c] = __expf(s[r][c] - mnew);
                ps += p[r][c];
            }
            ps += __shfl_xor_sync(0xffffffffu, ps, 1);
            ps += __shfl_xor_sync(0xffffffffu, ps, 2);
            ps += __shfl_xor_sync(0xffffffffu, ps, 4);
            ps += __shfl_xor_sync(0xffffffffu, ps, 8);
            l_i[r] = l_i[r]*corr + ps;
            m_i[r] = mnew;
            u64 cb = bcast2(corr);
            o2[r][0] = mul2(o2[r][0], cb);
            o2[r][1] = mul2(o2[r][1], cb);
        }

        // store P into KT buffer, layout P[kcol][qrow] with qgroup XOR-swizzle
#pragma unroll
        for (int c = 0; c < 4; c++) {
            float4 w = make_float4(p[0][c], p[1][c], p[2][c], p[3][c]);
            *(float4*)&KT[(tx*4 + c)*64 + ((ty ^ tx) * 4)] = w;
        }
        __syncthreads();

        // PV: o[r][c] += sum_k P[k][ty*4+r] * V[k][tx*4+c] — packed over c
#pragma unroll 8
        for (int kk = 0; kk < 64; kk++) {
            float4 pv = *(float4*)&KT[kk*64 + ((ty ^ (kk >> 2)) * 4)];
            ulonglong2 vp = *(ulonglong2*)&Vs[kk*64 + tx*4];
            float pa[4] = {pv.x, pv.y, pv.z, pv.w};
#pragma unroll
            for (int r = 0; r < 4; r++) {
                u64 pb = bcast2(pa[r]);
                o2[r][0] = fma2(pb, vp.x, o2[r][0]);
                o2[r][1] = fma2(pb, vp.y, o2[r][1]);
            }
        }
    }

    // write ctx
#pragma unroll
    for (int r = 0; r < 4; r++) {
        float inv = 1.f / l_i[r];
        int srow = q0 + ty*4 + r;
        float2 lo = upk(o2[r][0]), hi = upk(o2[r][1]);
        float4 w = make_float4(lo.x*inv, lo.y*inv, hi.x*inv, hi.y*inv);
        *(float4*)&g_ctx[base + (size_t)srow*LDGL + tx*4] = w;
    }
}

// ---------------- launch ----------------
extern "C" void kernel_launch(void* const* d_in, const int* in_sizes, int n_in,
                              void* d_out, int out_size) {
    const float* qx   = (const float*)d_in[0];
    const float* kx   = (const float*)d_in[1];
    const float* vx   = (const float*)d_in[2];
    const float* qc   = (const float*)d_in[3];
    const float* kc   = (const float*)d_in[4];
    const float* W_qx = (const float*)d_in[5];
    const float* b_qx = (const float*)d_in[6];
    const float* W_kx = (const float*)d_in[7];
    const float* b_kx = (const float*)d_in[8];
    const float* W_vx = (const float*)d_in[9];
    const float* b_vx = (const float*)d_in[10];
    const float* W_qc = (const float*)d_in[11];
    const float* b_qc = (const float*)d_in[12];
    const float* W_kc = (const float*)d_in[13];
    const float* b_kc = (const float*)d_in[14];
    const float* W_out= (const float*)d_in[15];
    const float* b_out= (const float*)d_in[16];
    const float* W_Vqx= (const float*)d_in[17];
    const float* b_Vqx= (const float*)d_in[18];
    const float* W_Vqc= (const float*)d_in[19];
    const float* b_Vqc= (const float*)d_in[20];
    const float* W_Vkx= (const float*)d_in[21];
    const float* b_Vkx= (const float*)d_in[22];
    const float* W_Vkc= (const float*)d_in[23];
    const float* b_Vkc= (const float*)d_in[24];

    float *p_qx, *p_kx, *p_vx, *p_qc, *p_kc, *p_ctx;
    cudaGetSymbolAddress((void**)&p_qx,  g_qx);
    cudaGetSymbolAddress((void**)&p_kx,  g_kx);
    cudaGetSymbolAddress((void**)&p_vx,  g_vx);
    cudaGetSymbolAddress((void**)&p_qc,  g_qc);
    cudaGetSymbolAddress((void**)&p_kc,  g_kc);
    cudaGetSymbolAddress((void**)&p_ctx, g_ctx);

    // 1) five input projections, batched over blockIdx.z
    Gemm5 ga;
    ga.g[0] = {qx, W_qx, b_qx, p_qx};
    ga.g[1] = {kx, W_kx, b_kx, p_kx};
    ga.g[2] = {vx, W_vx, b_vx, p_vx};
    ga.g[3] = {qc, W_qc, b_qc, p_qc};
    ga.g[4] = {kc, W_kc, b_kc, p_kc};
    sgemm_kernel<<<dim3(8, 32, 5), 256>>>(ga);

    // 2) lambda gates + mixing (in place into g_qx / g_kx)
    lam_mix_kernel<<<dim3(NROW, 2), 256>>>(W_Vqx, b_Vqx, W_Vqc, b_Vqc,
                                           W_Vkx, b_Vkx, W_Vkc, b_Vkc);

    // 3) attention
    flash_kernel<<<dim3(32, HEADS, BATCH), 256, 49152>>>();

    // 4) output projection straight into d_out
    Gemm5 go;
    go.g[0] = {p_ctx, W_out, b_out, (float*)d_out};
    go.g[1] = go.g[0]; go.g[2] = go.g[0]; go.g[3] = go.g[0]; go.g[4] = go.g[0];
    sgemm_kernel<<<dim3(8, 32, 1), 256>>>(go);
}

// round 5
// speedup vs baseline: 1.2666x; 1.2024x over previous
#include <cuda_runtime.h>
#include <cuda_bf16.h>
#include <math.h>
#include <stdint.h>

#define SEQ   2048
#define BATCH 2
#define DIM   1024
#define HEADS 16
#define DKH   64
#define NROW  (SEQ*BATCH)   // 4096
#define LDGL  (BATCH*DIM)   // 2048 floats between consecutive s

typedef unsigned long long u64;

// ---------------- packed f32x2 helpers (flash kernel) ----------------
__device__ __forceinline__ u64 bcast2(float x) {
    u64 r; asm("mov.b64 %0, {%1,%1};" : "=l"(r) : "f"(x)); return r;
}
__device__ __forceinline__ u64 fma2(u64 a, u64 b, u64 c) {
    u64 d; asm("fma.rn.f32x2 %0, %1, %2, %3;" : "=l"(d) : "l"(a), "l"(b), "l"(c)); return d;
}
__device__ __forceinline__ u64 mul2(u64 a, u64 b) {
    u64 d; asm("mul.rn.f32x2 %0, %1, %2;" : "=l"(d) : "l"(a), "l"(b)); return d;
}
__device__ __forceinline__ float2 upk(u64 v) {
    float2 f; asm("mov.b64 {%0,%1}, %2;" : "=f"(f.x), "=f"(f.y) : "l"(v)); return f;
}

// ---------------- mma.sync helpers (portable sm_80+ ISA) ----------------
__device__ __forceinline__ uint32_t smem_to_u32(const void* p) {
    uint32_t a;
    asm("{ .reg .u64 t; cvta.to.shared.u64 t, %1; cvt.u32.u64 %0, t; }" : "=r"(a) : "l"(p));
    return a;
}
__device__ __forceinline__ void cpasync16(uint32_t s, const void* g) {
    asm volatile("cp.async.cg.shared.global [%0], [%1], 16;" :: "r"(s), "l"(g) : "memory");
}
__device__ __forceinline__ void ldsm4(uint32_t* r, uint32_t addr) {
    asm volatile("ldmatrix.sync.aligned.m8n8.x4.shared.b16 {%0,%1,%2,%3}, [%4];"
        : "=r"(r[0]), "=r"(r[1]), "=r"(r[2]), "=r"(r[3]) : "r"(addr));
}
__device__ __forceinline__ void mma16816(float* d, const uint32_t* a, const uint32_t* b) {
    asm volatile("mma.sync.aligned.m16n8k16.row.col.f32.bf16.bf16.f32 "
        "{%0,%1,%2,%3}, {%4,%5,%6,%7}, {%8,%9}, {%0,%1,%2,%3};"
        : "+f"(d[0]), "+f"(d[1]), "+f"(d[2]), "+f"(d[3])
        : "r"(a[0]), "r"(a[1]), "r"(a[2]), "r"(a[3]), "r"(b[0]), "r"(b[1]));
}

// ---------------- scratch (device globals; no allocation allowed) ----------------
__device__ float g_qx[NROW*DIM];
__device__ float g_kx[NROW*DIM];
__device__ float g_vx[NROW*DIM];
__device__ float g_qc[NROW*DIM];
__device__ float g_kc[NROW*DIM];
__device__ float g_ctx[NROW*DIM];
__device__ __nv_bfloat16 g_sA[5*2*NROW*DIM];   // 5 inputs x 2 planes
__device__ __nv_bfloat16 g_sW[6*2*DIM*DIM];    // 6 weights (transposed) x 2 planes
__device__ __nv_bfloat16 g_sC[2*NROW*DIM];     // ctx x 2 planes

// ================= split2: fp32 -> bf16 hi/lo planes =================
__global__ __launch_bounds__(256)
void split2_kernel(const float4* __restrict__ in, __nv_bfloat16* __restrict__ o1,
                   __nv_bfloat16* __restrict__ o2, int n4) {
    int i = blockIdx.x * blockDim.x + threadIdx.x;
    if (i >= n4) return;
    float4 v = in[i];
    float vv[4] = {v.x, v.y, v.z, v.w};
    union { __nv_bfloat16 h[4]; uint2 u; } p1, p2;
#pragma unroll
    for (int k = 0; k < 4; k++) {
        __nv_bfloat16 a1 = __float2bfloat16(vv[k]);
        float r  = vv[k] - __bfloat162float(a1);
        p1.h[k] = a1; p2.h[k] = __float2bfloat16(r);
    }
    *(uint2*)(o1 + 4*(size_t)i) = p1.u;
    *(uint2*)(o2 + 4*(size_t)i) = p2.u;
}

// ================= weight transpose + split: W[K,N] -> WT planes [N,K] =================
struct WArg  { const float* W; __nv_bfloat16 *o1, *o2; };
struct WArgs { WArg w[6]; };
__global__ __launch_bounds__(256)
void wsplit_kernel(WArgs a) {
    __shared__ float tile[32][33];
    WArg wa = a.w[blockIdx.z];
    int tx = threadIdx.x, ty = threadIdx.y;    // 32 x 8
    int x = blockIdx.x * 32 + tx;              // n
    int yb = blockIdx.y * 32;                  // k base
#pragma unroll
    for (int j = 0; j < 32; j += 8)
        tile[ty + j][tx] = wa.W[(size_t)(yb + ty + j) * DIM + x];
    __syncthreads();
    int xo = blockIdx.y * 32 + tx;             // k out
    int yo = blockIdx.x * 32;                  // n out base
#pragma unroll
    for (int j = 0; j < 32; j += 8) {
        float v = tile[tx][ty + j];
        size_t o = (size_t)(yo + ty + j) * DIM + xo;
        __nv_bfloat16 b1 = __float2bfloat16(v);
        float r  = v - __bfloat162float(b1);
        wa.o1[o] = b1; wa.o2[o] = __float2bfloat16(r);
    }
}

// ================= HMMA bf16x2 GEMM: C[4096,1024] = A @ W + bias =================
// 128x128 tile, BK=32, 8 warps (warp tile 32x64), 4-stage cp.async pipeline.
// 3 term passes over K: (A1,W1), (A2,W1), (A1,W2) accumulated in fp32.
#define BM 128
#define BN 128
#define BK 32
#define PITCHB 80                         // bytes per smem row (40 bf16): conflict-free ldmatrix
#define STAGE_BYTES (2*128*PITCHB)        // A tile + B tile = 20480
#define STAGES 4
#define GEMM_SMEM (STAGES*STAGE_BYTES)    // 81920

struct GArg  { const __nv_bfloat16* A[2]; const __nv_bfloat16* B[2]; const float* bias; float* C; };
struct GArgs { GArg g[5]; };

__global__ __launch_bounds__(256, 1)
void gemm_mma_kernel(GArgs args) {
    extern __shared__ char smem[];
    const uint32_t sb = smem_to_u32(smem);
    GArg ga = args.g[blockIdx.z];
    const int t = threadIdx.x;
    const int wid = t >> 5, lane = t & 31;
    const int wm = wid & 3, wn = wid >> 2;        // 4 x 2 warps, warp tile 32x64
    const int m0 = blockIdx.y * BM, n0 = blockIdx.x * BN;
    const int NCH = 96;                           // 3 terms x 32 k-chunks

    float acc[2][8][4];
#pragma unroll
    for (int i = 0; i < 2; i++)
#pragma unroll
        for (int j = 0; j < 8; j++)
#pragma unroll
            for (int k = 0; k < 4; k++) acc[i][j][k] = 0.f;

    auto issue = [&](int c) {
        const int term = c >> 5, kc = (c & 31) * BK;
        const int ta[3] = {0, 1, 0}, tb[3] = {0, 0, 1};
        const __nv_bfloat16* Ap = ga.A[ta[term]];
        const __nv_bfloat16* Bp = ga.B[tb[term]];
        const uint32_t st  = sb + (c & (STAGES-1)) * STAGE_BYTES;
        const uint32_t stb = st + 128 * PITCHB;
#pragma unroll
        for (int i = 0; i < 2; i++) {
            int e = t + i * 256;
            int row = e >> 2, ch = e & 3;
            cpasync16(st + row * PITCHB + ch * 16,
                      Ap + (size_t)(m0 + row) * DIM + kc + ch * 8);
        }
#pragma unroll
        for (int i = 0; i < 2; i++) {
            int e = t + i * 256;
            int row = e >> 2, ch = e & 3;
            cpasync16(stb + row * PITCHB + ch * 16,
                      Bp + (size_t)(n0 + row) * DIM + kc + ch * 8);
        }
        asm volatile("cp.async.commit_group;" ::: "memory");
    };

    issue(0); issue(1); issue(2);

    for (int c = 0; c < NCH; c++) {
        if (c + 3 < NCH) {
            issue(c + 3);
            asm volatile("cp.async.wait_group 3;" ::: "memory");
        } else if (c + 2 < NCH) {
            asm volatile("cp.async.wait_group 2;" ::: "memory");
        } else if (c + 1 < NCH) {
            asm volatile("cp.async.wait_group 1;" ::: "memory");
        } else {
            asm volatile("cp.async.wait_group 0;" ::: "memory");
        }
        __syncthreads();

        const uint32_t st  = sb + (c & (STAGES-1)) * STAGE_BYTES;
        const uint32_t stb = st + 128 * PITCHB;
#pragma unroll
        for (int ks = 0; ks < 2; ks++) {
            const int kc2 = ks * 16;
            uint32_t af[2][4];
#pragma unroll
            for (int tm = 0; tm < 2; tm++) {
                int arow = wm*32 + tm*16 + (lane & 7) + ((lane >> 3) & 1) * 8;
                int acolb = (kc2 + ((lane >> 4) & 1) * 8) * 2;
                ldsm4(af[tm], st + arow * PITCHB + acolb);
            }
            uint32_t bfr[4][4];
#pragma unroll
            for (int g = 0; g < 4; g++) {
                int brow = wn*64 + g*16 + (lane & 7) + ((lane >> 4) & 1) * 8;
                int bcolb = (kc2 + ((lane >> 3) & 1) * 8) * 2;
                ldsm4(bfr[g], stb + brow * PITCHB + bcolb);
            }
#pragma unroll
            for (int tm = 0; tm < 2; tm++)
#pragma unroll
                for (int tn = 0; tn < 8; tn++)
                    mma16816(acc[tm][tn], af[tm], &bfr[tn >> 1][(tn & 1) * 2]);
        }
        __syncthreads();   // reads done before this stage is refilled
    }

    // epilogue: fragment layout -> C + bias (float2 stores)
#pragma unroll
    for (int tm = 0; tm < 2; tm++) {
        int r0 = m0 + wm*32 + tm*16 + lane / 4;
#pragma unroll
        for (int tn = 0; tn < 8; tn++) {
            int cc = n0 + wn*64 + tn*8 + (lane % 4) * 2;
            float2 bv = *(const float2*)&ga.bias[cc];
            float2 v0 = make_float2(acc[tm][tn][0] + bv.x, acc[tm][tn][1] + bv.y);
            float2 v1 = make_float2(acc[tm][tn][2] + bv.x, acc[tm][tn][3] + bv.y);
            *(float2*)&ga.C[(size_t)r0 * DIM + cc] = v0;
            *(float2*)&ga.C[(size_t)(r0 + 8) * DIM + cc] = v1;
        }
    }
}

// ---------------- lambda gate + mix (in place) ----------------
__global__ __launch_bounds__(256)
void lam_mix_kernel(const float* __restrict__ Wvqx, const float* __restrict__ bvqx,
                    const float* __restrict__ Wvqc, const float* __restrict__ bvqc,
                    const float* __restrict__ Wvkx, const float* __restrict__ bvkx,
                    const float* __restrict__ Wvkc, const float* __restrict__ bvkc) {
    const int r   = blockIdx.x;
    const bool isK = (blockIdx.y != 0);
    float* a = isK ? g_kx : g_qx;
    float* c = isK ? g_kc : g_qc;
    const float* Wa = isK ? Wvkx : Wvqx;
    const float* Wc = isK ? Wvkc : Wvqc;
    const float bsum = isK ? (bvkx[0] + bvkc[0]) : (bvqx[0] + bvqc[0]);

    const int t = threadIdx.x;
    float av[4], cv[4];
    float part = 0.f;
#pragma unroll
    for (int i = 0; i < 4; i++) {
        int d = t + i*256;
        av[i] = a[(size_t)r*1024 + d];
        cv[i] = c[(size_t)r*1024 + d];
        part += av[i]*Wa[d] + cv[i]*Wc[d];
    }
    __shared__ float red[256];
    red[t] = part;
    __syncthreads();
    for (int s = 128; s > 0; s >>= 1) {
        if (t < s) red[t] += red[t+s];
        __syncthreads();
    }
    float lam = 1.f / (1.f + __expf(-(red[0] + bsum)));
#pragma unroll
    for (int i = 0; i < 4; i++) {
        int d = t + i*256;
        a[(size_t)r*1024 + d] = av[i] + lam*(cv[i] - av[i]);
    }
}

// ---------------- fp32 flash attention (f32x2-packed math) ----------------
__global__ __launch_bounds__(256)
void flash_kernel() {
    extern __shared__ float sm[];
    float* QT = sm;
    float* KT = sm + 4096;
    float* Vs = sm + 8192;

    const int tid = threadIdx.x;
    const int tx = tid & 15, ty = tid >> 4;
    const int qt = blockIdx.x, h = blockIdx.y, b = blockIdx.z;
    const int q0 = qt * 64;
    const size_t base = (size_t)b * DIM + (size_t)h * DKH;

    {
        int row = tid & 63, cg = tid >> 6;
#pragma unroll
        for (int j = 0; j < 4; j++) {
            float4 v4 = *(const float4*)&g_qx[base + (size_t)(q0+row)*LDGL + cg*16 + j*4];
            QT[(cg*16 + j*4 + 0)*64 + row] = v4.x;
            QT[(cg*16 + j*4 + 1)*64 + row] = v4.y;
            QT[(cg*16 + j*4 + 2)*64 + row] = v4.z;
            QT[(cg*16 + j*4 + 3)*64 + row] = v4.w;
        }
    }

    float m_i[4], l_i[4];
    u64 o2[4][2];
#pragma unroll
    for (int r = 0; r < 4; r++) {
        m_i[r] = -1e30f; l_i[r] = 0.f;
        o2[r][0] = 0ull; o2[r][1] = 0ull;
    }

    for (int kt = 0; kt < 32; kt++) {
        const int k0 = kt * 64;
        __syncthreads();
        {
            int row = tid & 63, cg = tid >> 6;
#pragma unroll
            for (int j = 0; j < 4; j++) {
                float4 v4 = *(const float4*)&g_kx[base + (size_t)(k0+row)*LDGL + cg*16 + j*4];
                KT[(cg*16 + j*4 + 0)*64 + row] = v4.x;
                KT[(cg*16 + j*4 + 1)*64 + row] = v4.y;
                KT[(cg*16 + j*4 + 2)*64 + row] = v4.z;
                KT[(cg*16 + j*4 + 3)*64 + row] = v4.w;
            }
        }
        {
            int vr = tid >> 4, vc4 = tid & 15;
#pragma unroll
            for (int j = 0; j < 4; j++) {
                int row = vr + j*16;
                float4 v4 = *(const float4*)&g_vx[base + (size_t)(k0+row)*LDGL + vc4*4];
                *(float4*)&Vs[row*64 + vc4*4] = v4;
            }
        }
        __syncthreads();

        u64 s2[4][2];
#pragma unroll
        for (int r = 0; r < 4; r++) { s2[r][0] = 0ull; s2[r][1] = 0ull; }
#pragma unroll 8
        for (int d = 0; d < 64; d++) {
            float4 qv = *(float4*)&QT[d*64 + ty*4];
            ulonglong2 kp = *(ulonglong2*)&KT[d*64 + tx*4];
            float qa[4] = {qv.x, qv.y, qv.z, qv.w};
#pragma unroll
            for (int r = 0; r < 4; r++) {
                u64 qb = bcast2(qa[r]);
                s2[r][0] = fma2(qb, kp.x, s2[r][0]);
                s2[r][1] = fma2(qb, kp.y, s2[r][1]);
            }
        }
        float s[4][4];
#pragma unroll
        for (int r = 0; r < 4; r++) {
            float2 lo = upk(s2[r][0]), hi = upk(s2[r][1]);
            s[r][0] = lo.x*0.125f; s[r][1] = lo.y*0.125f;
            s[r][2] = hi.x*0.125f; s[r][3] = hi.y*0.125f;
        }

        __syncthreads();

        float p[4][4];
#pragma unroll
        for (int r = 0; r < 4; r++) {
            float mt = fmaxf(fmaxf(s[r][0], s[r][1]), fmaxf(s[r][2], s[r][3]));
            mt = fmaxf(mt, __shfl_xor_sync(0xffffffffu, mt, 1));
            mt = fmaxf(mt, __shfl_xor_sync(0xffffffffu, mt, 2));
            mt = fmaxf(mt, __shfl_xor_sync(0xffffffffu, mt, 4));
            mt = fmaxf(mt, __shfl_xor_sync(0xffffffffu, mt, 8));
            float mnew = fmaxf(m_i[r], mt);
            float corr = __expf(m_i[r] - mnew);
            float ps = 0.f;
#pragma unroll
            for (int c = 0; c < 4; c++) {
                p[r][c] = __expf(s[r][c] - mnew);
                ps += p[r][c];
            }
            ps += __shfl_xor_sync(0xffffffffu, ps, 1);
            ps += __shfl_xor_sync(0xffffffffu, ps, 2);
            ps += __shfl_xor_sync(0xffffffffu, ps, 4);
            ps += __shfl_xor_sync(0xffffffffu, ps, 8);
            l_i[r] = l_i[r]*corr + ps;
            m_i[r] = mnew;
            u64 cb = bcast2(corr);
            o2[r][0] = mul2(o2[r][0], cb);
            o2[r][1] = mul2(o2[r][1], cb);
        }

#pragma unroll
        for (int c = 0; c < 4; c++) {
            float4 w = make_float4(p[0][c], p[1][c], p[2][c], p[3][c]);
            *(float4*)&KT[(tx*4 + c)*64 + ((ty ^ tx) * 4)] = w;
        }
        __syncthreads();

#pragma unroll 8
        for (int kk = 0; kk < 64; kk++) {
            float4 pv = *(float4*)&KT[kk*64 + ((ty ^ (kk >> 2)) * 4)];
            ulonglong2 vp = *(ulonglong2*)&Vs[kk*64 + tx*4];
            float pa[4] = {pv.x, pv.y, pv.z, pv.w};
#pragma unroll
            for (int r = 0; r < 4; r++) {
                u64 pb = bcast2(pa[r]);
                o2[r][0] = fma2(pb, vp.x, o2[r][0]);
                o2[r][1] = fma2(pb, vp.y, o2[r][1]);
            }
        }
    }

#pragma unroll
    for (int r = 0; r < 4; r++) {
        float inv = 1.f / l_i[r];
        int srow = q0 + ty*4 + r;
        float2 lo = upk(o2[r][0]), hi = upk(o2[r][1]);
        float4 w = make_float4(lo.x*inv, lo.y*inv, hi.x*inv, hi.y*inv);
        *(float4*)&g_ctx[base + (size_t)srow*LDGL + tx*4] = w;
    }
}

// ---------------- launch ----------------
extern "C" void kernel_launch(void* const* d_in, const int* in_sizes, int n_in,
                              void* d_out, int out_size) {
    const float* in5[5]  = {(const float*)d_in[0], (const float*)d_in[1], (const float*)d_in[2],
                            (const float*)d_in[3], (const float*)d_in[4]};
    const float* W6[6]   = {(const float*)d_in[5],  (const float*)d_in[7],  (const float*)d_in[9],
                            (const float*)d_in[11], (const float*)d_in[13], (const float*)d_in[15]};
    const float* bias6[6]= {(const float*)d_in[6],  (const float*)d_in[8],  (const float*)d_in[10],
                            (const float*)d_in[12], (const float*)d_in[14], (const float*)d_in[16]};
    const float* W_Vqx= (const float*)d_in[17];
    const float* b_Vqx= (const float*)d_in[18];
    const float* W_Vqc= (const float*)d_in[19];
    const float* b_Vqc= (const float*)d_in[20];
    const float* W_Vkx= (const float*)d_in[21];
    const float* b_Vkx= (const float*)d_in[22];
    const float* W_Vkc= (const float*)d_in[23];
    const float* b_Vkc= (const float*)d_in[24];

    float *p_out5[5], *p_ctx;
    cudaGetSymbolAddress((void**)&p_out5[0], g_qx);
    cudaGetSymbolAddress((void**)&p_out5[1], g_kx);
    cudaGetSymbolAddress((void**)&p_out5[2], g_vx);
    cudaGetSymbolAddress((void**)&p_out5[3], g_qc);
    cudaGetSymbolAddress((void**)&p_out5[4], g_kc);
    cudaGetSymbolAddress((void**)&p_ctx,     g_ctx);
    __nv_bfloat16 *pA, *pW, *pC;
    cudaGetSymbolAddress((void**)&pA, g_sA);
    cudaGetSymbolAddress((void**)&pW, g_sW);
    cudaGetSymbolAddress((void**)&pC, g_sC);

    const size_t NA = (size_t)NROW * DIM;   // 4M elems
    const size_t NW = (size_t)DIM * DIM;    // 1M elems
    const int n4 = (int)(NA / 4);

    // 1) split inputs into bf16 hi/lo planes
    for (int i = 0; i < 5; i++)
        split2_kernel<<<n4/256, 256>>>((const float4*)in5[i],
                                       pA + (size_t)(i*2+0)*NA,
                                       pA + (size_t)(i*2+1)*NA, n4);

    // 2) transpose + split weights
    WArgs wa;
    for (int i = 0; i < 6; i++)
        wa.w[i] = { W6[i], pW + (size_t)(i*2+0)*NW, pW + (size_t)(i*2+1)*NW };
    wsplit_kernel<<<dim3(32, 32, 6), dim3(32, 8)>>>(wa);

    // 3) five projections on HMMA tensor cores
    cudaFuncSetAttribute(gemm_mma_kernel, cudaFuncAttributeMaxDynamicSharedMemorySize, GEMM_SMEM);
    GArgs ga;
    for (int i = 0; i < 5; i++) {
        GArg g;
        for (int p = 0; p < 2; p++) {
            g.A[p] = pA + (size_t)(i*2+p)*NA;
            g.B[p] = pW + (size_t)(i*2+p)*NW;
        }
        g.bias = bias6[i];
        g.C = p_out5[i];
        ga.g[i] = g;
    }
    gemm_mma_kernel<<<dim3(8, 32, 5), 256, GEMM_SMEM>>>(ga);

    // 4) lambda gates + mixing
    lam_mix_kernel<<<dim3(NROW, 2), 256>>>(W_Vqx, b_Vqx, W_Vqc, b_Vqc,
                                           W_Vkx, b_Vkx, W_Vkc, b_Vkc);

    // 5) attention
    flash_kernel<<<dim3(32, HEADS, BATCH), 256, 49152>>>();

    // 6) split ctx, then output projection into d_out
    split2_kernel<<<n4/256, 256>>>((const float4*)p_ctx, pC, pC + NA, n4);
    GArgs go;
    {
        GArg g;
        for (int p = 0; p < 2; p++) {
            g.A[p] = pC + (size_t)p*NA;
            g.B[p] = pW + (size_t)(5*2+p)*NW;
        }
        g.bias = bias6[5];
        g.C = (float*)d_out;
        go.g[0] = g;
        go.g[1] = g; go.g[2] = g; go.g[3] = g; go.g[4] = g;
    }
    gemm_mma_kernel<<<dim3(8, 32, 1), 256, GEMM_SMEM>>>(go);
}

// round 6
// speedup vs baseline: 1.9807x; 1.5638x over previous
#include <cuda_runtime.h>
#include <cuda_bf16.h>
#include <math.h>
#include <stdint.h>

#define SEQ   2048
#define BATCH 2
#define DIM   1024
#define HEADS 16
#define DKH   64
#define NROW  (SEQ*BATCH)   // 4096
#define BH    (BATCH*HEADS) // 32

typedef unsigned long long u64;

// ---------------- mma.sync helpers (portable sm_80+ ISA) ----------------
__device__ __forceinline__ uint32_t smem_to_u32(const void* p) {
    uint32_t a;
    asm("{ .reg .u64 t; cvta.to.shared.u64 t, %1; cvt.u32.u64 %0, t; }" : "=r"(a) : "l"(p));
    return a;
}
__device__ __forceinline__ void cpasync16(uint32_t s, const void* g) {
    asm volatile("cp.async.cg.shared.global [%0], [%1], 16;" :: "r"(s), "l"(g) : "memory");
}
__device__ __forceinline__ void ldsm4(uint32_t* r, uint32_t addr) {
    asm volatile("ldmatrix.sync.aligned.m8n8.x4.shared.b16 {%0,%1,%2,%3}, [%4];"
        : "=r"(r[0]), "=r"(r[1]), "=r"(r[2]), "=r"(r[3]) : "r"(addr));
}
__device__ __forceinline__ void mma16816(float* d, const uint32_t* a, const uint32_t* b) {
    asm volatile("mma.sync.aligned.m16n8k16.row.col.f32.bf16.bf16.f32 "
        "{%0,%1,%2,%3}, {%4,%5,%6,%7}, {%8,%9}, {%0,%1,%2,%3};"
        : "+f"(d[0]), "+f"(d[1]), "+f"(d[2]), "+f"(d[3])
        : "r"(a[0]), "r"(a[1]), "r"(a[2]), "r"(a[3]), "r"(b[0]), "r"(b[1]));
}
// pack (lo=a, hi=b) into bf16x2
__device__ __forceinline__ uint32_t pack2(float lo, float hi) {
    uint32_t r; asm("cvt.rn.bf16x2.f32 %0, %1, %2;" : "=r"(r) : "f"(hi), "f"(lo)); return r;
}

// ---------------- scratch (device globals; no allocation allowed) ----------------
__device__ float g_qx[NROW*DIM];
__device__ float g_kx[NROW*DIM];
__device__ float g_vx[NROW*DIM];
__device__ float g_qc[NROW*DIM];
__device__ float g_kc[NROW*DIM];
__device__ float g_ctx[NROW*DIM];
__device__ __nv_bfloat16 g_sA[5*2*NROW*DIM];
__device__ __nv_bfloat16 g_sW[6*2*DIM*DIM];
__device__ __nv_bfloat16 g_sC[2*NROW*DIM];
// attention operand planes, layout [bh][s][dk] (q,k) and [bh][dk][s] (v transposed)
__device__ __nv_bfloat16 g_qh[BH*SEQ*DKH];
__device__ __nv_bfloat16 g_ql[BH*SEQ*DKH];
__device__ __nv_bfloat16 g_kh[BH*SEQ*DKH];
__device__ __nv_bfloat16 g_kl[BH*SEQ*DKH];
__device__ __nv_bfloat16 g_vth[BH*DKH*SEQ];
__device__ __nv_bfloat16 g_vtl[BH*DKH*SEQ];

// ================= split2: fp32 -> bf16 hi/lo planes =================
__global__ __launch_bounds__(256)
void split2_kernel(const float4* __restrict__ in, __nv_bfloat16* __restrict__ o1,
                   __nv_bfloat16* __restrict__ o2, int n4) {
    int i = blockIdx.x * blockDim.x + threadIdx.x;
    if (i >= n4) return;
    float4 v = in[i];
    float vv[4] = {v.x, v.y, v.z, v.w};
    union { __nv_bfloat16 h[4]; uint2 u; } p1, p2;
#pragma unroll
    for (int k = 0; k < 4; k++) {
        __nv_bfloat16 a1 = __float2bfloat16(vv[k]);
        float r  = vv[k] - __bfloat162float(a1);
        p1.h[k] = a1; p2.h[k] = __float2bfloat16(r);
    }
    *(uint2*)(o1 + 4*(size_t)i) = p1.u;
    *(uint2*)(o2 + 4*(size_t)i) = p2.u;
}

// ================= weight transpose + split =================
struct WArg  { const float* W; __nv_bfloat16 *o1, *o2; };
struct WArgs { WArg w[6]; };
__global__ __launch_bounds__(256)
void wsplit_kernel(WArgs a) {
    __shared__ float tile[32][33];
    WArg wa = a.w[blockIdx.z];
    int tx = threadIdx.x, ty = threadIdx.y;
    int x = blockIdx.x * 32 + tx;
    int yb = blockIdx.y * 32;
#pragma unroll
    for (int j = 0; j < 32; j += 8)
        tile[ty + j][tx] = wa.W[(size_t)(yb + ty + j) * DIM + x];
    __syncthreads();
    int xo = blockIdx.y * 32 + tx;
    int yo = blockIdx.x * 32;
#pragma unroll
    for (int j = 0; j < 32; j += 8) {
        float v = tile[tx][ty + j];
        size_t o = (size_t)(yo + ty + j) * DIM + xo;
        __nv_bfloat16 b1 = __float2bfloat16(v);
        float r  = v - __bfloat162float(b1);
        wa.o1[o] = b1; wa.o2[o] = __float2bfloat16(r);
    }
}

// ================= HMMA bf16x2 GEMM (unchanged from R5) =================
#define BM 128
#define BN 128
#define BK 32
#define PITCHB 80
#define STAGE_BYTES (2*128*PITCHB)
#define STAGES 4
#define GEMM_SMEM (STAGES*STAGE_BYTES)

struct GArg  { const __nv_bfloat16* A[2]; const __nv_bfloat16* B[2]; const float* bias; float* C; };
struct GArgs { GArg g[5]; };

__global__ __launch_bounds__(256, 1)
void gemm_mma_kernel(GArgs args) {
    extern __shared__ char smem[];
    const uint32_t sb = smem_to_u32(smem);
    GArg ga = args.g[blockIdx.z];
    const int t = threadIdx.x;
    const int wid = t >> 5, lane = t & 31;
    const int wm = wid & 3, wn = wid >> 2;
    const int m0 = blockIdx.y * BM, n0 = blockIdx.x * BN;
    const int NCH = 96;

    float acc[2][8][4];
#pragma unroll
    for (int i = 0; i < 2; i++)
#pragma unroll
        for (int j = 0; j < 8; j++)
#pragma unroll
            for (int k = 0; k < 4; k++) acc[i][j][k] = 0.f;

    auto issue = [&](int c) {
        const int term = c >> 5, kc = (c & 31) * BK;
        const int ta[3] = {0, 1, 0}, tb[3] = {0, 0, 1};
        const __nv_bfloat16* Ap = ga.A[ta[term]];
        const __nv_bfloat16* Bp = ga.B[tb[term]];
        const uint32_t st  = sb + (c & (STAGES-1)) * STAGE_BYTES;
        const uint32_t stb = st + 128 * PITCHB;
#pragma unroll
        for (int i = 0; i < 2; i++) {
            int e = t + i * 256;
            int row = e >> 2, ch = e & 3;
            cpasync16(st + row * PITCHB + ch * 16,
                      Ap + (size_t)(m0 + row) * DIM + kc + ch * 8);
        }
#pragma unroll
        for (int i = 0; i < 2; i++) {
            int e = t + i * 256;
            int row = e >> 2, ch = e & 3;
            cpasync16(stb + row * PITCHB + ch * 16,
                      Bp + (size_t)(n0 + row) * DIM + kc + ch * 8);
        }
        asm volatile("cp.async.commit_group;" ::: "memory");
    };

    issue(0); issue(1); issue(2);

    for (int c = 0; c < NCH; c++) {
        if (c + 3 < NCH) {
            issue(c + 3);
            asm volatile("cp.async.wait_group 3;" ::: "memory");
        } else if (c + 2 < NCH) {
            asm volatile("cp.async.wait_group 2;" ::: "memory");
        } else if (c + 1 < NCH) {
            asm volatile("cp.async.wait_group 1;" ::: "memory");
        } else {
            asm volatile("cp.async.wait_group 0;" ::: "memory");
        }
        __syncthreads();

        const uint32_t st  = sb + (c & (STAGES-1)) * STAGE_BYTES;
        const uint32_t stb = st + 128 * PITCHB;
#pragma unroll
        for (int ks = 0; ks < 2; ks++) {
            const int kc2 = ks * 16;
            uint32_t af[2][4];
#pragma unroll
            for (int tm = 0; tm < 2; tm++) {
                int arow = wm*32 + tm*16 + (lane & 15);
                int acolb = (kc2 + ((lane >> 4) & 1) * 8) * 2;
                ldsm4(af[tm], st + arow * PITCHB + acolb);
            }
            uint32_t bfr[4][4];
#pragma unroll
            for (int g = 0; g < 4; g++) {
                int brow = wn*64 + g*16 + (lane & 7) + ((lane >> 4) & 1) * 8;
                int bcolb = (kc2 + ((lane >> 3) & 1) * 8) * 2;
                ldsm4(bfr[g], stb + brow * PITCHB + bcolb);
            }
#pragma unroll
            for (int tm = 0; tm < 2; tm++)
#pragma unroll
                for (int tn = 0; tn < 8; tn++)
                    mma16816(acc[tm][tn], af[tm], &bfr[tn >> 1][(tn & 1) * 2]);
        }
        __syncthreads();
    }

#pragma unroll
    for (int tm = 0; tm < 2; tm++) {
        int r0 = m0 + wm*32 + tm*16 + lane / 4;
#pragma unroll
        for (int tn = 0; tn < 8; tn++) {
            int cc = n0 + wn*64 + tn*8 + (lane % 4) * 2;
            float2 bv = *(const float2*)&ga.bias[cc];
            float2 v0 = make_float2(acc[tm][tn][0] + bv.x, acc[tm][tn][1] + bv.y);
            float2 v1 = make_float2(acc[tm][tn][2] + bv.x, acc[tm][tn][3] + bv.y);
            *(float2*)&ga.C[(size_t)r0 * DIM + cc] = v0;
            *(float2*)&ga.C[(size_t)(r0 + 8) * DIM + cc] = v1;
        }
    }
}

// ---------------- lambda gate + mix -> bf16 planes [bh][s][dk] ----------------
__global__ __launch_bounds__(256)
void lam_mix_kernel(const float* __restrict__ Wvqx, const float* __restrict__ bvqx,
                    const float* __restrict__ Wvqc, const float* __restrict__ bvqc,
                    const float* __restrict__ Wvkx, const float* __restrict__ bvkx,
                    const float* __restrict__ Wvkc, const float* __restrict__ bvkc) {
    const int r   = blockIdx.x;
    const bool isK = (blockIdx.y != 0);
    const float* a = isK ? g_kx : g_qx;
    const float* c = isK ? g_kc : g_qc;
    const float* Wa = isK ? Wvkx : Wvqx;
    const float* Wc = isK ? Wvkc : Wvqc;
    const float bsum = isK ? (bvkx[0] + bvkc[0]) : (bvqx[0] + bvqc[0]);
    __nv_bfloat16* oh = isK ? g_kh : g_qh;
    __nv_bfloat16* ol = isK ? g_kl : g_ql;

    const int t = threadIdx.x;
    const int s = r >> 1, b = r & 1;
    float av[4], cv[4];
    float part = 0.f;
#pragma unroll
    for (int i = 0; i < 4; i++) {
        int d = t + i*256;
        av[i] = a[(size_t)r*1024 + d];
        cv[i] = c[(size_t)r*1024 + d];
        part += av[i]*Wa[d] + cv[i]*Wc[d];
    }
    __shared__ float red[256];
    red[t] = part;
    __syncthreads();
    for (int ss = 128; ss > 0; ss >>= 1) {
        if (t < ss) red[t] += red[t+ss];
        __syncthreads();
    }
    float lam = 1.f / (1.f + __expf(-(red[0] + bsum)));
#pragma unroll
    for (int i = 0; i < 4; i++) {
        int d = t + i*256;
        float m = av[i] + lam*(cv[i] - av[i]);
        int hh = d >> 6, dk = d & 63;
        size_t off = ((size_t)(b*HEADS + hh)*SEQ + s)*DKH + dk;
        __nv_bfloat16 mh = __float2bfloat16(m);
        oh[off] = mh;
        ol[off] = __float2bfloat16(m - __bfloat162float(mh));
    }
}

// ---------------- V transpose + split: g_vx -> Vt planes [bh][dk][s] ----------------
__global__ __launch_bounds__(256)
void vsplit_kernel() {
    __shared__ float tile[64][65];
    const int t = threadIdx.x;
    const int s0 = blockIdx.x * 64, bh = blockIdx.y;
    const int b = bh >> 4, h = bh & 15;
#pragma unroll
    for (int i = 0; i < 4; i++) {
        int e = i*256 + t;
        int sr = e >> 4, c4 = e & 15;
        float4 v = *(const float4*)&g_vx[((size_t)(s0+sr)*BATCH + b)*DIM + h*DKH + c4*4];
        tile[sr][c4*4+0] = v.x; tile[sr][c4*4+1] = v.y;
        tile[sr][c4*4+2] = v.z; tile[sr][c4*4+3] = v.w;
    }
    __syncthreads();
    const int dkr = t >> 2, sc = (t & 3) * 16;
    union { __nv_bfloat16 h[8]; uint4 u; } hp[2], lp[2];
#pragma unroll
    for (int ch = 0; ch < 2; ch++)
#pragma unroll
        for (int k = 0; k < 8; k++) {
            float v = tile[sc + ch*8 + k][dkr];
            __nv_bfloat16 hb = __float2bfloat16(v);
            hp[ch].h[k] = hb;
            lp[ch].h[k] = __float2bfloat16(v - __bfloat162float(hb));
        }
    size_t off = ((size_t)bh*DKH + dkr)*SEQ + s0 + sc;
    *(uint4*)&g_vth[off] = hp[0].u; *(uint4*)&g_vth[off+8] = hp[1].u;
    *(uint4*)&g_vtl[off] = lp[0].u; *(uint4*)&g_vtl[off+8] = lp[1].u;
}

// ---------------- HMMA flash attention ----------------
// grid (16 qtiles, 32 bh); 256 thr (8 warps x 16 q-rows). Bq=128, Bk=64.
// smem: Qh 16K | Ql 16K | KV stages x2: {Kh 8K | Kl 8K | Vh 8K | Vl 8K}
#define FL_SMEM (32768 + 2*32768)
#define SWZ(row, c16) ((row)*128 + ((((c16) ^ ((row)&7)))<<4))

__global__ __launch_bounds__(256)
void flash_mma_kernel() {
    extern __shared__ char fsm[];
    const uint32_t sb = smem_to_u32(fsm);
    const int t = threadIdx.x, lane = t & 31, w = t >> 5;
    const int q0 = blockIdx.x * 128, bh = blockIdx.y;
    const int row0 = w * 16;

    // Q load (both planes)
    {
        size_t qoff = ((size_t)bh*SEQ + q0)*DKH;
#pragma unroll
        for (int i = 0; i < 8; i++) {
            int e = i*256 + t;
            int c16 = e & 7, row = (e >> 3) & 127, pl = e >> 10;
            const __nv_bfloat16* src = (pl ? g_ql : g_qh) + qoff + row*DKH + c16*8;
            cpasync16(sb + pl*16384 + SWZ(row, c16), src);
        }
        asm volatile("cp.async.commit_group;" ::: "memory");
    }
    auto issue_kv = [&](int kt, int st) {
        int k0 = kt * 64;
#pragma unroll
        for (int i = 0; i < 8; i++) {
            int e = i*256 + t;
            int c16 = e & 7, row = (e >> 3) & 63, pl = e >> 9;
            const __nv_bfloat16* src;
            if (pl < 2) src = (pl ? g_kl : g_kh) + ((size_t)bh*SEQ + k0 + row)*DKH + c16*8;
            else src = (pl == 3 ? g_vtl : g_vth) + ((size_t)bh*DKH + row)*SEQ + k0 + c16*8;
            cpasync16(sb + 32768 + st*32768 + pl*8192 + SWZ(row, c16), src);
        }
        asm volatile("cp.async.commit_group;" ::: "memory");
    };
    issue_kv(0, 0);

    float m0r = -1e30f, m1r = -1e30f, l0 = 0.f, l1 = 0.f;
    float oacc[8][4];
#pragma unroll
    for (int j = 0; j < 8; j++)
#pragma unroll
        for (int k = 0; k < 4; k++) oacc[j][k] = 0.f;

    for (int kt = 0; kt < 32; kt++) {
        const int st = kt & 1;
        if (kt + 1 < 32) {
            issue_kv(kt + 1, st ^ 1);
            asm volatile("cp.async.wait_group 1;" ::: "memory");
        } else {
            asm volatile("cp.async.wait_group 0;" ::: "memory");
        }
        __syncthreads();

        const uint32_t Kh = sb + 32768 + st*32768;
        const uint32_t Kl = Kh + 8192, Vh = Kh + 16384, Vl = Kh + 24576;

        // ---- S = Q K^T (3 split terms) ----
        float sacc[8][4];
#pragma unroll
        for (int j = 0; j < 8; j++)
#pragma unroll
            for (int k = 0; k < 4; k++) sacc[j][k] = 0.f;

#pragma unroll
        for (int ks = 0; ks < 4; ks++) {
            uint32_t a1[4], a2[4];
            {
                int r = row0 + (lane & 15);
                int c16 = ks*2 + ((lane >> 4) & 1);
                ldsm4(a1, sb + SWZ(r, c16));
                ldsm4(a2, sb + 16384 + SWZ(r, c16));
            }
            uint32_t bb[4][4];
            int br = (lane & 7) + ((lane >> 4) & 1) * 8;
            int bc16 = ks*2 + ((lane >> 3) & 1);
#pragma unroll
            for (int g = 0; g < 4; g++) { int rr = g*16 + br; ldsm4(bb[g], Kh + SWZ(rr, bc16)); }
#pragma unroll
            for (int j = 0; j < 8; j++) mma16816(sacc[j], a1, &bb[j>>1][(j&1)*2]);
#pragma unroll
            for (int j = 0; j < 8; j++) mma16816(sacc[j], a2, &bb[j>>1][(j&1)*2]);
#pragma unroll
            for (int g = 0; g < 4; g++) { int rr = g*16 + br; ldsm4(bb[g], Kl + SWZ(rr, bc16)); }
#pragma unroll
            for (int j = 0; j < 8; j++) mma16816(sacc[j], a1, &bb[j>>1][(j&1)*2]);
        }

        // ---- online softmax (rows: lane>>2 and +8) ----
        float mx0 = -1e30f, mx1 = -1e30f;
#pragma unroll
        for (int j = 0; j < 8; j++) {
#pragma unroll
            for (int k = 0; k < 4; k++) sacc[j][k] *= 0.125f;
            mx0 = fmaxf(mx0, fmaxf(sacc[j][0], sacc[j][1]));
            mx1 = fmaxf(mx1, fmaxf(sacc[j][2], sacc[j][3]));
        }
        mx0 = fmaxf(mx0, __shfl_xor_sync(0xffffffffu, mx0, 1));
        mx0 = fmaxf(mx0, __shfl_xor_sync(0xffffffffu, mx0, 2));
        mx1 = fmaxf(mx1, __shfl_xor_sync(0xffffffffu, mx1, 1));
        mx1 = fmaxf(mx1, __shfl_xor_sync(0xffffffffu, mx1, 2));
        float mn0 = fmaxf(m0r, mx0), mn1 = fmaxf(m1r, mx1);
        float corr0 = __expf(m0r - mn0), corr1 = __expf(m1r - mn1);
        m0r = mn0; m1r = mn1;
        float rs0 = 0.f, rs1 = 0.f;
#pragma unroll
        for (int j = 0; j < 8; j++) {
            sacc[j][0] = __expf(sacc[j][0] - mn0);
            sacc[j][1] = __expf(sacc[j][1] - mn0);
            sacc[j][2] = __expf(sacc[j][2] - mn1);
            sacc[j][3] = __expf(sacc[j][3] - mn1);
            rs0 += sacc[j][0] + sacc[j][1];
            rs1 += sacc[j][2] + sacc[j][3];
            oacc[j][0] *= corr0; oacc[j][1] *= corr0;
            oacc[j][2] *= corr1; oacc[j][3] *= corr1;
        }
        rs0 += __shfl_xor_sync(0xffffffffu, rs0, 1);
        rs0 += __shfl_xor_sync(0xffffffffu, rs0, 2);
        rs1 += __shfl_xor_sync(0xffffffffu, rs1, 1);
        rs1 += __shfl_xor_sync(0xffffffffu, rs1, 2);
        l0 = l0*corr0 + rs0;
        l1 = l1*corr1 + rs1;

        // ---- pack P into A-frags (hi + residual lo) ----
        uint32_t ph[4][4], pl[4][4];
#pragma unroll
        for (int ks = 0; ks < 4; ks++) {
            int j0 = 2*ks, j1 = 2*ks + 1;
            float p00 = sacc[j0][0], p01 = sacc[j0][1], p02 = sacc[j0][2], p03 = sacc[j0][3];
            float p10 = sacc[j1][0], p11 = sacc[j1][1], p12 = sacc[j1][2], p13 = sacc[j1][3];
            uint32_t h0 = pack2(p00, p01), h1 = pack2(p02, p03);
            uint32_t h2 = pack2(p10, p11), h3 = pack2(p12, p13);
            ph[ks][0] = h0; ph[ks][1] = h1; ph[ks][2] = h2; ph[ks][3] = h3;
            pl[ks][0] = pack2(p00 - __uint_as_float(h0 << 16), p01 - __uint_as_float(h0 & 0xffff0000u));
            pl[ks][1] = pack2(p02 - __uint_as_float(h1 << 16), p03 - __uint_as_float(h1 & 0xffff0000u));
            pl[ks][2] = pack2(p10 - __uint_as_float(h2 << 16), p11 - __uint_as_float(h2 & 0xffff0000u));
            pl[ks][3] = pack2(p12 - __uint_as_float(h3 << 16), p13 - __uint_as_float(h3 & 0xffff0000u));
        }

        // ---- O += P V (3 split terms); Vt is [dk][kcol] so B-operand is direct ----
#pragma unroll
        for (int ks = 0; ks < 4; ks++) {
            uint32_t bb[4][4];
            int br = (lane & 7) + ((lane >> 4) & 1) * 8;
            int bc16 = ks*2 + ((lane >> 3) & 1);
#pragma unroll
            for (int g = 0; g < 4; g++) { int rr = g*16 + br; ldsm4(bb[g], Vh + SWZ(rr, bc16)); }
#pragma unroll
            for (int j = 0; j < 8; j++) mma16816(oacc[j], ph[ks], &bb[j>>1][(j&1)*2]);
#pragma unroll
            for (int j = 0; j < 8; j++) mma16816(oacc[j], pl[ks], &bb[j>>1][(j&1)*2]);
#pragma unroll
            for (int g = 0; g < 4; g++) { int rr = g*16 + br; ldsm4(bb[g], Vl + SWZ(rr, bc16)); }
#pragma unroll
            for (int j = 0; j < 8; j++) mma16816(oacc[j], ph[ks], &bb[j>>1][(j&1)*2]);
        }
        __syncthreads();   // all reads of this stage done before next refill
    }

    // ---- epilogue: write ctx fp32 [s*B+b][h*64+dk] ----
    const float inv0 = 1.f / l0, inv1 = 1.f / l1;
    const int b = bh >> 4, h = bh & 15;
    const int sg = q0 + row0 + (lane >> 2);
#pragma unroll
    for (int j = 0; j < 8; j++) {
        int dk = j*8 + (lane & 3)*2;
        float2 v0 = make_float2(oacc[j][0]*inv0, oacc[j][1]*inv0);
        float2 v1 = make_float2(oacc[j][2]*inv1, oacc[j][3]*inv1);
        *(float2*)&g_ctx[((size_t)sg*BATCH + b)*DIM + h*DKH + dk] = v0;
        *(float2*)&g_ctx[((size_t)(sg+8)*BATCH + b)*DIM + h*DKH + dk] = v1;
    }
}

// ---------------- launch ----------------
extern "C" void kernel_launch(void* const* d_in, const int* in_sizes, int n_in,
                              void* d_out, int out_size) {
    const float* in5[5]  = {(const float*)d_in[0], (const float*)d_in[1], (const float*)d_in[2],
                            (const float*)d_in[3], (const float*)d_in[4]};
    const float* W6[6]   = {(const float*)d_in[5],  (const float*)d_in[7],  (const float*)d_in[9],
                            (const float*)d_in[11], (const float*)d_in[13], (const float*)d_in[15]};
    const float* bias6[6]= {(const float*)d_in[6],  (const float*)d_in[8],  (const float*)d_in[10],
                            (const float*)d_in[12], (const float*)d_in[14], (const float*)d_in[16]};
    const float* W_Vqx= (const float*)d_in[17];
    const float* b_Vqx= (const float*)d_in[18];
    const float* W_Vqc= (const float*)d_in[19];
    const float* b_Vqc= (const float*)d_in[20];
    const float* W_Vkx= (const float*)d_in[21];
    const float* b_Vkx= (const float*)d_in[22];
    const float* W_Vkc= (const float*)d_in[23];
    const float* b_Vkc= (const float*)d_in[24];

    float *p_out5[5], *p_ctx;
    cudaGetSymbolAddress((void**)&p_out5[0], g_qx);
    cudaGetSymbolAddress((void**)&p_out5[1], g_kx);
    cudaGetSymbolAddress((void**)&p_out5[2], g_vx);
    cudaGetSymbolAddress((void**)&p_out5[3], g_qc);
    cudaGetSymbolAddress((void**)&p_out5[4], g_kc);
    cudaGetSymbolAddress((void**)&p_ctx,     g_ctx);
    __nv_bfloat16 *pA, *pW, *pC;
    cudaGetSymbolAddress((void**)&pA, g_sA);
    cudaGetSymbolAddress((void**)&pW, g_sW);
    cudaGetSymbolAddress((void**)&pC, g_sC);

    const size_t NA = (size_t)NROW * DIM;
    const size_t NW = (size_t)DIM * DIM;
    const int n4 = (int)(NA / 4);

    // 1) split inputs into bf16 hi/lo planes
    for (int i = 0; i < 5; i++)
        split2_kernel<<<n4/256, 256>>>((const float4*)in5[i],
                                       pA + (size_t)(i*2+0)*NA,
                                       pA + (size_t)(i*2+1)*NA, n4);

    // 2) transpose + split weights
    WArgs wa;
    for (int i = 0; i < 6; i++)
        wa.w[i] = { W6[i], pW + (size_t)(i*2+0)*NW, pW + (size_t)(i*2+1)*NW };
    wsplit_kernel<<<dim3(32, 32, 6), dim3(32, 8)>>>(wa);

    // 3) five projections on HMMA tensor cores
    cudaFuncSetAttribute(gemm_mma_kernel, cudaFuncAttributeMaxDynamicSharedMemorySize, GEMM_SMEM);
    GArgs ga;
    for (int i = 0; i < 5; i++) {
        GArg g;
        for (int p = 0; p < 2; p++) {
            g.A[p] = pA + (size_t)(i*2+p)*NA;
            g.B[p] = pW + (size_t)(i*2+p)*NW;
        }
        g.bias = bias6[i];
        g.C = p_out5[i];
        ga.g[i] = g;
    }
    gemm_mma_kernel<<<dim3(8, 32, 5), 256, GEMM_SMEM>>>(ga);

    // 4) lambda gates + mixing -> bf16 planes; V transpose+split
    lam_mix_kernel<<<dim3(NROW, 2), 256>>>(W_Vqx, b_Vqx, W_Vqc, b_Vqc,
                                           W_Vkx, b_Vkx, W_Vkc, b_Vkc);
    vsplit_kernel<<<dim3(SEQ/64, BH), 256>>>();

    // 5) HMMA flash attention
    cudaFuncSetAttribute(flash_mma_kernel, cudaFuncAttributeMaxDynamicSharedMemorySize, FL_SMEM);
    flash_mma_kernel<<<dim3(SEQ/128, BH), 256, FL_SMEM>>>();

    // 6) split ctx, then output projection into d_out
    split2_kernel<<<n4/256, 256>>>((const float4*)p_ctx, pC, pC + NA, n4);
    GArgs go;
    {
        GArg g;
        for (int p = 0; p < 2; p++) {
            g.A[p] = pC + (size_t)p*NA;
            g.B[p] = pW + (size_t)(5*2+p)*NW;
        }
        g.bias = bias6[5];
        g.C = (float*)d_out;
        go.g[0] = g;
        go.g[1] = g; go.g[2] = g; go.g[3] = g; go.g[4] = g;
    }
    gemm_mma_kernel<<<dim3(8, 32, 1), 256, GEMM_SMEM>>>(go);
}

// round 8
// speedup vs baseline: 2.9635x; 1.4962x over previous
#include <cuda_runtime.h>
#include <cuda_bf16.h>
#include <math.h>
#include <stdint.h>

#define SEQ   2048
#define BATCH 2
#define DIM   1024
#define HEADS 16
#define DKH   64
#define NROW  (SEQ*BATCH)   // 4096
#define BH    (BATCH*HEADS) // 32

typedef unsigned long long u64;

// ---------------- mma.sync helpers (portable sm_80+ ISA) ----------------
__device__ __forceinline__ uint32_t smem_to_u32(const void* p) {
    uint32_t a;
    asm("{ .reg .u64 t; cvta.to.shared.u64 t, %1; cvt.u32.u64 %0, t; }" : "=r"(a) : "l"(p));
    return a;
}
__device__ __forceinline__ void cpasync16(uint32_t s, const void* g) {
    asm volatile("cp.async.cg.shared.global [%0], [%1], 16;" :: "r"(s), "l"(g) : "memory");
}
__device__ __forceinline__ void ldsm4(uint32_t* r, uint32_t addr) {
    asm volatile("ldmatrix.sync.aligned.m8n8.x4.shared.b16 {%0,%1,%2,%3}, [%4];"
        : "=r"(r[0]), "=r"(r[1]), "=r"(r[2]), "=r"(r[3]) : "r"(addr));
}
__device__ __forceinline__ void mma16816(float* d, const uint32_t* a, const uint32_t* b) {
    asm volatile("mma.sync.aligned.m16n8k16.row.col.f32.bf16.bf16.f32 "
        "{%0,%1,%2,%3}, {%4,%5,%6,%7}, {%8,%9}, {%0,%1,%2,%3};"
        : "+f"(d[0]), "+f"(d[1]), "+f"(d[2]), "+f"(d[3])
        : "r"(a[0]), "r"(a[1]), "r"(a[2]), "r"(a[3]), "r"(b[0]), "r"(b[1]));
}
// pack (lo=a, hi=b) into bf16x2
__device__ __forceinline__ uint32_t pack2(float lo, float hi) {
    uint32_t r; asm("cvt.rn.bf16x2.f32 %0, %1, %2;" : "=r"(r) : "f"(hi), "f"(lo)); return r;
}

#define SWZ(row, c16) ((row)*128 + ((((c16) ^ ((row)&7)))<<4))

// ---------------- scratch (device globals; no allocation allowed) ----------------
__device__ float g_qx[NROW*DIM];
__device__ float g_kx[NROW*DIM];
__device__ float g_vx[NROW*DIM];
__device__ float g_qc[NROW*DIM];
__device__ float g_kc[NROW*DIM];
__device__ float g_ctx[NROW*DIM];
__device__ __nv_bfloat16 g_sA[5*2*NROW*DIM];
__device__ __nv_bfloat16 g_sW[6*2*DIM*DIM];
__device__ __nv_bfloat16 g_sC[2*NROW*DIM];
__device__ __nv_bfloat16 g_qh[BH*SEQ*DKH];
__device__ __nv_bfloat16 g_ql[BH*SEQ*DKH];
__device__ __nv_bfloat16 g_kh[BH*SEQ*DKH];
__device__ __nv_bfloat16 g_kl[BH*SEQ*DKH];
__device__ __nv_bfloat16 g_vth[BH*DKH*SEQ];
__device__ __nv_bfloat16 g_vtl[BH*DKH*SEQ];

// ================= split2: fp32 -> bf16 hi/lo planes =================
__global__ __launch_bounds__(256)
void split2_kernel(const float4* __restrict__ in, __nv_bfloat16* __restrict__ o1,
                   __nv_bfloat16* __restrict__ o2, int n4) {
    int i = blockIdx.x * blockDim.x + threadIdx.x;
    if (i >= n4) return;
    float4 v = in[i];
    float vv[4] = {v.x, v.y, v.z, v.w};
    union { __nv_bfloat16 h[4]; uint2 u; } p1, p2;
#pragma unroll
    for (int k = 0; k < 4; k++) {
        __nv_bfloat16 a1 = __float2bfloat16(vv[k]);
        float r  = vv[k] - __bfloat162float(a1);
        p1.h[k] = a1; p2.h[k] = __float2bfloat16(r);
    }
    *(uint2*)(o1 + 4*(size_t)i) = p1.u;
    *(uint2*)(o2 + 4*(size_t)i) = p2.u;
}

// ================= weight transpose + split =================
struct WArg  { const float* W; __nv_bfloat16 *o1, *o2; };
struct WArgs { WArg w[6]; };
__global__ __launch_bounds__(256)
void wsplit_kernel(WArgs a) {
    __shared__ float tile[32][33];
    WArg wa = a.w[blockIdx.z];
    int tx = threadIdx.x, ty = threadIdx.y;
    int x = blockIdx.x * 32 + tx;
    int yb = blockIdx.y * 32;
#pragma unroll
    for (int j = 0; j < 32; j += 8)
        tile[ty + j][tx] = wa.W[(size_t)(yb + ty + j) * DIM + x];
    __syncthreads();
    int xo = blockIdx.y * 32 + tx;
    int yo = blockIdx.x * 32;
#pragma unroll
    for (int j = 0; j < 32; j += 8) {
        float v = tile[tx][ty + j];
        size_t o = (size_t)(yo + ty + j) * DIM + xo;
        __nv_bfloat16 b1 = __float2bfloat16(v);
        float r  = v - __bfloat162float(b1);
        wa.o1[o] = b1; wa.o2[o] = __float2bfloat16(r);
    }
}

// ================= HMMA bf16x2 GEMM v2: fused split terms =================
// 128x128 tile, BK=64; per stage: A1|A2|B1|B2 (16KB each, swizzled 128B rows).
// 3 terms issued from the same resident tiles: 48 MMA / 12 LDSM per kstep.
#define GBK 64
#define TILE_B 16384
#define GSTAGE_B (4*TILE_B)        // 65536
#define GSTAGES 3
#define GEMM_SMEM (GSTAGES*GSTAGE_B)  // 196608
#define GNCH 16

struct GArg  { const __nv_bfloat16* A[2]; const __nv_bfloat16* B[2]; const float* bias; float* C; };
struct GArgs { GArg g[5]; };

__global__ __launch_bounds__(256, 1)
void gemm_mma_kernel(GArgs args) {
    extern __shared__ char smem[];
    const uint32_t sb = smem_to_u32(smem);
    GArg ga = args.g[blockIdx.z];
    const int t = threadIdx.x;
    const int wid = t >> 5, lane = t & 31;
    const int wm = wid & 3, wn = wid >> 2;      // 4 x 2 warps, warp tile 32x64
    const int m0 = blockIdx.y * 128, n0 = blockIdx.x * 128;

    float acc[2][8][4];
#pragma unroll
    for (int i = 0; i < 2; i++)
#pragma unroll
        for (int j = 0; j < 8; j++)
#pragma unroll
            for (int k = 0; k < 4; k++) acc[i][j][k] = 0.f;

    auto issue = [&](int c) {
        const int kc = c * GBK;
        const uint32_t st = sb + (c % GSTAGES) * GSTAGE_B;
        const __nv_bfloat16* srcs[4] = {ga.A[0], ga.A[1], ga.B[0], ga.B[1]};
#pragma unroll
        for (int tile = 0; tile < 4; tile++) {
            const __nv_bfloat16* base = srcs[tile];
            const int rbase = (tile < 2) ? m0 : n0;
#pragma unroll
            for (int i = 0; i < 4; i++) {
                int e = i * 256 + t;
                int c16 = e & 7, row = e >> 3;
                cpasync16(st + tile * TILE_B + SWZ(row, c16),
                          base + (size_t)(rbase + row) * DIM + kc + c16 * 8);
            }
        }
        asm volatile("cp.async.commit_group;" ::: "memory");
    };

    issue(0); issue(1);

    for (int c = 0; c < GNCH; c++) {
        if (c + 2 < GNCH) {
            issue(c + 2);
            asm volatile("cp.async.wait_group 2;" ::: "memory");
        } else if (c + 1 < GNCH) {
            asm volatile("cp.async.wait_group 1;" ::: "memory");
        } else {
            asm volatile("cp.async.wait_group 0;" ::: "memory");
        }
        __syncthreads();

        const uint32_t st = sb + (c % GSTAGES) * GSTAGE_B;
        const uint32_t A1 = st, A2 = st + TILE_B, B1 = st + 2*TILE_B, B2 = st + 3*TILE_B;
#pragma unroll
        for (int ks = 0; ks < 4; ks++) {
            uint32_t af1[2][4], af2[2][4];
            {
                int ar = wm*32 + (lane & 15);
                int ac16 = ks*2 + ((lane >> 4) & 1);
                ldsm4(af1[0], A1 + SWZ(ar,      ac16));
                ldsm4(af1[1], A1 + SWZ(ar + 16, ac16));
                ldsm4(af2[0], A2 + SWZ(ar,      ac16));
                ldsm4(af2[1], A2 + SWZ(ar + 16, ac16));
            }
            uint32_t bb1[4][4], bb2[4][4];
            {
                int br = (lane & 7) + ((lane >> 4) & 1) * 8;
                int bc16 = ks*2 + ((lane >> 3) & 1);
#pragma unroll
                for (int g = 0; g < 4; g++) {
                    int rr = wn*64 + g*16 + br;
                    ldsm4(bb1[g], B1 + SWZ(rr, bc16));
                    ldsm4(bb2[g], B2 + SWZ(rr, bc16));
                }
            }
#pragma unroll
            for (int tm = 0; tm < 2; tm++)
#pragma unroll
                for (int tn = 0; tn < 8; tn++) {
                    mma16816(acc[tm][tn], af1[tm], &bb1[tn >> 1][(tn & 1) * 2]);
                    mma16816(acc[tm][tn], af2[tm], &bb1[tn >> 1][(tn & 1) * 2]);
                    mma16816(acc[tm][tn], af1[tm], &bb2[tn >> 1][(tn & 1) * 2]);
                }
        }
        __syncthreads();
    }

    // epilogue: fragment layout -> C + bias (float2 stores)
#pragma unroll
    for (int tm = 0; tm < 2; tm++) {
        int r0 = m0 + wm*32 + tm*16 + lane / 4;
#pragma unroll
        for (int tn = 0; tn < 8; tn++) {
            int cc = n0 + wn*64 + tn*8 + (lane % 4) * 2;
            float2 bv = *(const float2*)&ga.bias[cc];
            float2 v0 = make_float2(acc[tm][tn][0] + bv.x, acc[tm][tn][1] + bv.y);
            float2 v1 = make_float2(acc[tm][tn][2] + bv.x, acc[tm][tn][3] + bv.y);
            *(float2*)&ga.C[(size_t)r0 * DIM + cc] = v0;
            *(float2*)&ga.C[(size_t)(r0 + 8) * DIM + cc] = v1;
        }
    }
}

// ---------------- lambda gate + mix -> bf16 planes [bh][s][dk] ----------------
__global__ __launch_bounds__(256)
void lam_mix_kernel(const float* __restrict__ Wvqx, const float* __restrict__ bvqx,
                    const float* __restrict__ Wvqc, const float* __restrict__ bvqc,
                    const float* __restrict__ Wvkx, const float* __restrict__ bvkx,
                    const float* __restrict__ Wvkc, const float* __restrict__ bvkc) {
    const int r   = blockIdx.x;
    const bool isK = (blockIdx.y != 0);
    const float* a = isK ? g_kx : g_qx;
    const float* c = isK ? g_kc : g_qc;
    const float* Wa = isK ? Wvkx : Wvqx;
    const float* Wc = isK ? Wvkc : Wvqc;
    const float bsum = isK ? (bvkx[0] + bvkc[0]) : (bvqx[0] + bvqc[0]);
    __nv_bfloat16* oh = isK ? g_kh : g_qh;
    __nv_bfloat16* ol = isK ? g_kl : g_ql;

    const int t = threadIdx.x;
    const int s = r >> 1, b = r & 1;
    float av[4], cv[4];
    float part = 0.f;
#pragma unroll
    for (int i = 0; i < 4; i++) {
        int d = t + i*256;
        av[i] = a[(size_t)r*1024 + d];
        cv[i] = c[(size_t)r*1024 + d];
        part += av[i]*Wa[d] + cv[i]*Wc[d];
    }
    __shared__ float red[256];
    red[t] = part;
    __syncthreads();
    for (int ss = 128; ss > 0; ss >>= 1) {
        if (t < ss) red[t] += red[t+ss];
        __syncthreads();
    }
    float lam = 1.f / (1.f + __expf(-(red[0] + bsum)));
#pragma unroll
    for (int i = 0; i < 4; i++) {
        int d = t + i*256;
        float m = av[i] + lam*(cv[i] - av[i]);
        int hh = d >> 6, dk = d & 63;
        size_t off = ((size_t)(b*HEADS + hh)*SEQ + s)*DKH + dk;
        __nv_bfloat16 mh = __float2bfloat16(m);
        oh[off] = mh;
        ol[off] = __float2bfloat16(m - __bfloat162float(mh));
    }
}

// ---------------- V transpose + split: g_vx -> Vt planes [bh][dk][s] ----------------
__global__ __launch_bounds__(256)
void vsplit_kernel() {
    __shared__ float tile[64][65];
    const int t = threadIdx.x;
    const int s0 = blockIdx.x * 64, bh = blockIdx.y;
    const int b = bh >> 4, h = bh & 15;
#pragma unroll
    for (int i = 0; i < 4; i++) {
        int e = i*256 + t;
        int sr = e >> 4, c4 = e & 15;
        float4 v = *(const float4*)&g_vx[((size_t)(s0+sr)*BATCH + b)*DIM + h*DKH + c4*4];
        tile[sr][c4*4+0] = v.x; tile[sr][c4*4+1] = v.y;
        tile[sr][c4*4+2] = v.z; tile[sr][c4*4+3] = v.w;
    }
    __syncthreads();
    const int dkr = t >> 2, sc = (t & 3) * 16;
    union { __nv_bfloat16 h[8]; uint4 u; } hp[2], lp[2];
#pragma unroll
    for (int ch = 0; ch < 2; ch++)
#pragma unroll
        for (int k = 0; k < 8; k++) {
            float v = tile[sc + ch*8 + k][dkr];
            __nv_bfloat16 hb = __float2bfloat16(v);
            hp[ch].h[k] = hb;
            lp[ch].h[k] = __float2bfloat16(v - __bfloat162float(hb));
        }
    size_t off = ((size_t)bh*DKH + dkr)*SEQ + s0 + sc;
    *(uint4*)&g_vth[off] = hp[0].u; *(uint4*)&g_vth[off+8] = hp[1].u;
    *(uint4*)&g_vtl[off] = lp[0].u; *(uint4*)&g_vtl[off+8] = lp[1].u;
}

// ---------------- HMMA flash attention ----------------
#define FL_SMEM (32768 + 2*32768)

__global__ __launch_bounds__(256)
void flash_mma_kernel() {
    extern __shared__ char fsm[];
    const uint32_t sb = smem_to_u32(fsm);
    const int t = threadIdx.x, lane = t & 31, w = t >> 5;
    const int q0 = blockIdx.x * 128, bh = blockIdx.y;
    const int row0 = w * 16;

    {
        size_t qoff = ((size_t)bh*SEQ + q0)*DKH;
#pragma unroll
        for (int i = 0; i < 8; i++) {
            int e = i*256 + t;
            int c16 = e & 7, row = (e >> 3) & 127, pl = e >> 10;
            const __nv_bfloat16* src = (pl ? g_ql : g_qh) + qoff + row*DKH + c16*8;
            cpasync16(sb + pl*16384 + SWZ(row, c16), src);
        }
        asm volatile("cp.async.commit_group;" ::: "memory");
    }
    auto issue_kv = [&](int kt, int st) {
        int k0 = kt * 64;
#pragma unroll
        for (int i = 0; i < 8; i++) {
            int e = i*256 + t;
            int c16 = e & 7, row = (e >> 3) & 63, pl = e >> 9;
            const __nv_bfloat16* src;
            if (pl < 2) src = (pl ? g_kl : g_kh) + ((size_t)bh*SEQ + k0 + row)*DKH + c16*8;
            else src = (pl == 3 ? g_vtl : g_vth) + ((size_t)bh*DKH + row)*SEQ + k0 + c16*8;
            cpasync16(sb + 32768 + st*32768 + pl*8192 + SWZ(row, c16), src);
        }
        asm volatile("cp.async.commit_group;" ::: "memory");
    };
    issue_kv(0, 0);

    float m0r = -1e30f, m1r = -1e30f, l0 = 0.f, l1 = 0.f;
    float oacc[8][4];
#pragma unroll
    for (int j = 0; j < 8; j++)
#pragma unroll
        for (int k = 0; k < 4; k++) oacc[j][k] = 0.f;

    for (int kt = 0; kt < 32; kt++) {
        const int st = kt & 1;
        if (kt + 1 < 32) {
            issue_kv(kt + 1, st ^ 1);
            asm volatile("cp.async.wait_group 1;" ::: "memory");
        } else {
            asm volatile("cp.async.wait_group 0;" ::: "memory");
        }
        __syncthreads();

        const uint32_t Kh = sb + 32768 + st*32768;
        const uint32_t Kl = Kh + 8192, Vh = Kh + 16384, Vl = Kh + 24576;

        float sacc[8][4];
#pragma unroll
        for (int j = 0; j < 8; j++)
#pragma unroll
            for (int k = 0; k < 4; k++) sacc[j][k] = 0.f;

#pragma unroll
        for (int ks = 0; ks < 4; ks++) {
            uint32_t a1[4], a2[4];
            {
                int r = row0 + (lane & 15);
                int c16 = ks*2 + ((lane >> 4) & 1);
                ldsm4(a1, sb + SWZ(r, c16));
                ldsm4(a2, sb + 16384 + SWZ(r, c16));
            }
            uint32_t bb[4][4];
            int br = (lane & 7) + ((lane >> 4) & 1) * 8;
            int bc16 = ks*2 + ((lane >> 3) & 1);
#pragma unroll
            for (int g = 0; g < 4; g++) { int rr = g*16 + br; ldsm4(bb[g], Kh + SWZ(rr, bc16)); }
#pragma unroll
            for (int j = 0; j < 8; j++) mma16816(sacc[j], a1, &bb[j>>1][(j&1)*2]);
#pragma unroll
            for (int j = 0; j < 8; j++) mma16816(sacc[j], a2, &bb[j>>1][(j&1)*2]);
#pragma unroll
            for (int g = 0; g < 4; g++) { int rr = g*16 + br; ldsm4(bb[g], Kl + SWZ(rr, bc16)); }
#pragma unroll
            for (int j = 0; j < 8; j++) mma16816(sacc[j], a1, &bb[j>>1][(j&1)*2]);
        }

        float mx0 = -1e30f, mx1 = -1e30f;
#pragma unroll
        for (int j = 0; j < 8; j++) {
#pragma unroll
            for (int k = 0; k < 4; k++) sacc[j][k] *= 0.125f;
            mx0 = fmaxf(mx0, fmaxf(sacc[j][0], sacc[j][1]));
            mx1 = fmaxf(mx1, fmaxf(sacc[j][2], sacc[j][3]));
        }
        mx0 = fmaxf(mx0, __shfl_xor_sync(0xffffffffu, mx0, 1));
        mx0 = fmaxf(mx0, __shfl_xor_sync(0xffffffffu, mx0, 2));
        mx1 = fmaxf(mx1, __shfl_xor_sync(0xffffffffu, mx1, 1));
        mx1 = fmaxf(mx1, __shfl_xor_sync(0xffffffffu, mx1, 2));
        float mn0 = fmaxf(m0r, mx0), mn1 = fmaxf(m1r, mx1);
        float corr0 = __expf(m0r - mn0), corr1 = __expf(m1r - mn1);
        m0r = mn0; m1r = mn1;
        float rs0 = 0.f, rs1 = 0.f;
#pragma unroll
        for (int j = 0; j < 8; j++) {
            sacc[j][0] = __expf(sacc[j][0] - mn0);
            sacc[j][1] = __expf(sacc[j][1] - mn0);
            sacc[j][2] = __expf(sacc[j][2] - mn1);
            sacc[j][3] = __expf(sacc[j][3] - mn1);
            rs0 += sacc[j][0] + sacc[j][1];
            rs1 += sacc[j][2] + sacc[j][3];
            oacc[j][0] *= corr0; oacc[j][1] *= corr0;
            oacc[j][2] *= corr1; oacc[j][3] *= corr1;
        }
        rs0 += __shfl_xor_sync(0xffffffffu, rs0, 1);
        rs0 += __shfl_xor_sync(0xffffffffu, rs0, 2);
        rs1 += __shfl_xor_sync(0xffffffffu, rs1, 1);
        rs1 += __shfl_xor_sync(0xffffffffu, rs1, 2);
        l0 = l0*corr0 + rs0;
        l1 = l1*corr1 + rs1;

        uint32_t ph[4][4], pl[4][4];
#pragma unroll
        for (int ks = 0; ks < 4; ks++) {
            int j0 = 2*ks, j1 = 2*ks + 1;
            float p00 = sacc[j0][0], p01 = sacc[j0][1], p02 = sacc[j0][2], p03 = sacc[j0][3];
            float p10 = sacc[j1][0], p11 = sacc[j1][1], p12 = sacc[j1][2], p13 = sacc[j1][3];
            uint32_t h0 = pack2(p00, p01), h1 = pack2(p02, p03);
            uint32_t h2 = pack2(p10, p11), h3 = pack2(p12, p13);
            ph[ks][0] = h0; ph[ks][1] = h1; ph[ks][2] = h2; ph[ks][3] = h3;
            pl[ks][0] = pack2(p00 - __uint_as_float(h0 << 16), p01 - __uint_as_float(h0 & 0xffff0000u));
            pl[ks][1] = pack2(p02 - __uint_as_float(h1 << 16), p03 - __uint_as_float(h1 & 0xffff0000u));
            pl[ks][2] = pack2(p10 - __uint_as_float(h2 << 16), p11 - __uint_as_float(h2 & 0xffff0000u));
            pl[ks][3] = pack2(p12 - __uint_as_float(h3 << 16), p13 - __uint_as_float(h3 & 0xffff0000u));
        }

#pragma unroll
        for (int ks = 0; ks < 4; ks++) {
            uint32_t bb[4][4];
            int br = (lane & 7) + ((lane >> 4) & 1) * 8;
            int bc16 = ks*2 + ((lane >> 3) & 1);
#pragma unroll
            for (int g = 0; g < 4; g++) { int rr = g*16 + br; ldsm4(bb[g], Vh + SWZ(rr, bc16)); }
#pragma unroll
            for (int j = 0; j < 8; j++) mma16816(oacc[j], ph[ks], &bb[j>>1][(j&1)*2]);
#pragma unroll
            for (int j = 0; j < 8; j++) mma16816(oacc[j], pl[ks], &bb[j>>1][(j&1)*2]);
#pragma unroll
            for (int g = 0; g < 4; g++) { int rr = g*16 + br; ldsm4(bb[g], Vl + SWZ(rr, bc16)); }
#pragma unroll
            for (int j = 0; j < 8; j++) mma16816(oacc[j], ph[ks], &bb[j>>1][(j&1)*2]);
        }
        __syncthreads();
    }

    const float inv0 = 1.f / l0, inv1 = 1.f / l1;
    const int b = bh >> 4, h = bh & 15;
    const int sg = q0 + row0 + (lane >> 2);
#pragma unroll
    for (int j = 0; j < 8; j++) {
        int dk = j*8 + (lane & 3)*2;
        float2 v0 = make_float2(oacc[j][0]*inv0, oacc[j][1]*inv0);
        float2 v1 = make_float2(oacc[j][2]*inv1, oacc[j][3]*inv1);
        *(float2*)&g_ctx[((size_t)sg*BATCH + b)*DIM + h*DKH + dk] = v0;
        *(float2*)&g_ctx[((size_t)(sg+8)*BATCH + b)*DIM + h*DKH + dk] = v1;
    }
}

// ---------------- launch ----------------
extern "C" void kernel_launch(void* const* d_in, const int* in_sizes, int n_in,
                              void* d_out, int out_size) {
    const float* in5[5]  = {(const float*)d_in[0], (const float*)d_in[1], (const float*)d_in[2],
                            (const float*)d_in[3], (const float*)d_in[4]};
    const float* W6[6]   = {(const float*)d_in[5],  (const float*)d_in[7],  (const float*)d_in[9],
                            (const float*)d_in[11], (const float*)d_in[13], (const float*)d_in[15]};
    const float* bias6[6]= {(const float*)d_in[6],  (const float*)d_in[8],  (const float*)d_in[10],
                            (const float*)d_in[12], (const float*)d_in[14], (const float*)d_in[16]};
    const float* W_Vqx= (const float*)d_in[17];
    const float* b_Vqx= (const float*)d_in[18];
    const float* W_Vqc= (const float*)d_in[19];
    const float* b_Vqc= (const float*)d_in[20];
    const float* W_Vkx= (const float*)d_in[21];
    const float* b_Vkx= (const float*)d_in[22];
    const float* W_Vkc= (const float*)d_in[23];
    const float* b_Vkc= (const float*)d_in[24];

    float *p_out5[5], *p_ctx;
    cudaGetSymbolAddress((void**)&p_out5[0], g_qx);
    cudaGetSymbolAddress((void**)&p_out5[1], g_kx);
    cudaGetSymbolAddress((void**)&p_out5[2], g_vx);
    cudaGetSymbolAddress((void**)&p_out5[3], g_qc);
    cudaGetSymbolAddress((void**)&p_out5[4], g_kc);
    cudaGetSymbolAddress((void**)&p_ctx,     g_ctx);
    __nv_bfloat16 *pA, *pW, *pC;
    cudaGetSymbolAddress((void**)&pA, g_sA);
    cudaGetSymbolAddress((void**)&pW, g_sW);
    cudaGetSymbolAddress((void**)&pC, g_sC);

    const size_t NA = (size_t)NROW * DIM;
    const size_t NW = (size_t)DIM * DIM;
    const int n4 = (int)(NA / 4);

    // 1) split inputs into bf16 hi/lo planes
    for (int i = 0; i < 5; i++)
        split2_kernel<<<n4/256, 256>>>((const float4*)in5[i],
                                       pA + (size_t)(i*2+0)*NA,
                                       pA + (size_t)(i*2+1)*NA, n4);

    // 2) transpose + split weights
    WArgs wa;
    for (int i = 0; i < 6; i++)
        wa.w[i] = { W6[i], pW + (size_t)(i*2+0)*NW, pW + (size_t)(i*2+1)*NW };
    wsplit_kernel<<<dim3(32, 32, 6), dim3(32, 8)>>>(wa);

    // 3) five projections on HMMA tensor cores
    cudaFuncSetAttribute(gemm_mma_kernel, cudaFuncAttributeMaxDynamicSharedMemorySize, GEMM_SMEM);
    GArgs ga;
    for (int i = 0; i < 5; i++) {
        GArg g;
        for (int p = 0; p < 2; p++) {
            g.A[p] = pA + (size_t)(i*2+p)*NA;
            g.B[p] = pW + (size_t)(i*2+p)*NW;
        }
        g.bias = bias6[i];
        g.C = p_out5[i];
        ga.g[i] = g;
    }
    gemm_mma_kernel<<<dim3(8, 32, 5), 256, GEMM_SMEM>>>(ga);

    // 4) lambda gates + mixing -> bf16 planes; V transpose+split
    lam_mix_kernel<<<dim3(NROW, 2), 256>>>(W_Vqx, b_Vqx, W_Vqc, b_Vqc,
                                           W_Vkx, b_Vkx, W_Vkc, b_Vkc);
    vsplit_kernel<<<dim3(SEQ/64, BH), 256>>>();

    // 5) HMMA flash attention
    cudaFuncSetAttribute(flash_mma_kernel, cudaFuncAttributeMaxDynamicSharedMemorySize, FL_SMEM);
    flash_mma_kernel<<<dim3(SEQ/128, BH), 256, FL_SMEM>>>();

    // 6) split ctx, then output projection into d_out
    split2_kernel<<<n4/256, 256>>>((const float4*)p_ctx, pC, pC + NA, n4);
    GArgs go;
    {
        GArg g;
        for (int p = 0; p < 2; p++) {
            g.A[p] = pC + (size_t)p*NA;
            g.B[p] = pW + (size_t)(5*2+p)*NW;
        }
        g.bias = bias6[5];
        g.C = (float*)d_out;
        go.g[0] = g;
        go.g[1] = g; go.g[2] = g; go.g[3] = g; go.g[4] = g;
    }
    gemm_mma_kernel<<<dim3(8, 32, 1), 256, GEMM_SMEM>>>(go);
}